// round 13
// baseline (speedup 1.0000x reference)
#include <cuda_runtime.h>
#include <cuda_fp16.h>
#include <cstdint>

// Problem dims (fixed)
#define BC   2
#define LC   1024
#define DM   1024
#define DI   2048
#define DS   16
#define DCNV 4
#define DTR  64
#define MROWS (BC*LC)      // 2048
#define NXZ   (2*DI)       // 4096
#define NDP   128

// ---------------- scratch (device globals) ----------------
__device__ float g_xz  [MROWS * NXZ];
__device__ float g_xc  [MROWS * DI];
__device__ float g_dt  [MROWS * DI];
__device__ float g_dbl [MROWS * NDP];
__device__ float g_dblp[8 * MROWS * NDP];
__device__ float g_osp [2 * MROWS * DM];

__device__ __half g_xh  [MROWS * DM];
__device__ __half g_Wih [DM * NXZ];
__device__ __half g_Wxh [DI * NDP],    g_Wxl [DI * NDP];
__device__ __half g_xch [MROWS * DI],  g_xcl [MROWS * DI];
__device__ __half g_dbh [MROWS * DTR], g_dbll[MROWS * DTR];
__device__ __half g_Wdh [DTR * DI],    g_Wdl [DTR * DI];
__device__ __half g_yh  [MROWS * DI];
__device__ __half g_Woh [DI * DM];

// ---------------------------------------------------------------------------
// helpers
// ---------------------------------------------------------------------------
__device__ __forceinline__ uint32_t pack_h2(float a, float b) {
    __half2 h = __floats2half2_rn(a, b);
    return *reinterpret_cast<uint32_t*>(&h);
}
__device__ __forceinline__ void split4(float4 v, uint2& H, uint2& L) {
    float hx = __half2float(__float2half(v.x));
    float hy = __half2float(__float2half(v.y));
    float hz = __half2float(__float2half(v.z));
    float hw = __half2float(__float2half(v.w));
    H.x = pack_h2(v.x, v.y);            H.y = pack_h2(v.z, v.w);
    L.x = pack_h2(v.x - hx, v.y - hy);  L.y = pack_h2(v.z - hz, v.w - hw);
}

// ---------------------------------------------------------------------------
// Fused conversion (round-11 version; segments in float4 units)
//   [0,SEG1): x -> xh (hi)             [SEG1,SEG2): W_in -> Wih (hi)
//   [SEG2,SEG3): W_dt -> hi/lo         [SEG3,SEG4): W_out -> Woh (hi)
//   [SEG4,SEG5): W_x -> hi/lo padded [DI x 128]
// ---------------------------------------------------------------------------
#define SEG1  524288
#define SEG2 1572864
#define SEG3 1605632
#define SEG4 2129920
#define SEG5 2195456

__global__ void prep_kernel(const float4* __restrict__ x,
                            const float4* __restrict__ W_in,
                            const float4* __restrict__ W_dt,
                            const float4* __restrict__ W_out,
                            const float*  __restrict__ W_x,
                            uint2* __restrict__ xh,
                            uint2* __restrict__ Wih,
                            uint2* __restrict__ Wdh, uint2* __restrict__ Wdl,
                            uint2* __restrict__ Woh,
                            uint2* __restrict__ Wxh, uint2* __restrict__ Wxl)
{
    int i = blockIdx.x * blockDim.x + threadIdx.x;
    if (i >= SEG5) return;
    if (i < SEG1) {
        float4 v = x[i];
        uint2 H; H.x = pack_h2(v.x, v.y); H.y = pack_h2(v.z, v.w);
        xh[i] = H;
    } else if (i < SEG2) {
        int j = i - SEG1;
        float4 v = W_in[j];
        uint2 H; H.x = pack_h2(v.x, v.y); H.y = pack_h2(v.z, v.w);
        Wih[j] = H;
    } else if (i < SEG3) {
        int j = i - SEG2;
        uint2 H, L; split4(W_dt[j], H, L);
        Wdh[j] = H; Wdl[j] = L;
    } else if (i < SEG4) {
        int j = i - SEG3;
        float4 v = W_out[j];
        uint2 H; H.x = pack_h2(v.x, v.y); H.y = pack_h2(v.z, v.w);
        Woh[j] = H;
    } else {
        int j = i - SEG4;
        int idx = j * 4;
        int r = idx >> 7, c = idx & 127;
        float4 v = (c < 96) ? *(const float4*)(W_x + (size_t)r * 96 + c)
                            : make_float4(0.f, 0.f, 0.f, 0.f);
        uint2 H, L; split4(v, H, L);
        Wxh[j] = H; Wxl[j] = L;
    }
}

// ---------------------------------------------------------------------------
// reduces
// ---------------------------------------------------------------------------
__global__ void reduce_dbl_kernel(const float* __restrict__ parts,
                                  float* __restrict__ dbl,
                                  __half* __restrict__ dbh,
                                  __half* __restrict__ dbll)
{
    int i = blockIdx.x * blockDim.x + threadIdx.x;
    if (i >= MROWS * NDP) return;
    float s = 0.f;
#pragma unroll
    for (int k = 0; k < 8; k++) s += parts[(size_t)k * MROWS * NDP + i];
    dbl[i] = s;
    int c = i & 127;
    if (c < 64) {
        int r = i >> 7;
        __half h = __float2half(s);
        dbh [r * DTR + c] = h;
        dbll[r * DTR + c] = __float2half(s - __half2float(h));
    }
}

__global__ void reduce_out_kernel(const float4* __restrict__ s0,
                                  const float4* __restrict__ s1,
                                  float4* __restrict__ out, int n4)
{
    int i = blockIdx.x * blockDim.x + threadIdx.x;
    if (i >= n4) return;
    float4 a = s0[i], b = s1[i];
    out[i] = make_float4(a.x + b.x, a.y + b.y, a.z + b.z, a.w + b.w);
}

// ---------------------------------------------------------------------------
// Tensor-core GEMM: 128x128 CTA, 256 threads (8 warps, 64x32 warp tile).
// TERMS = 1 (AhBh), 2 (+AlBh), 3 (+AhBl). BK=32, NS-stage cp.async.
// ---------------------------------------------------------------------------
#define AS_ST 40
#define BS_ST 136
#define A_PL  (128*AS_ST)
#define B_PL  (32*BS_ST)

__device__ __forceinline__ void cp16(uint32_t dst, const void* src) {
    asm volatile("cp.async.cg.shared.global [%0], [%1], 16;\n" :: "r"(dst), "l"(src));
}
__device__ __forceinline__ void ldsm4(uint32_t* r, uint32_t addr) {
    asm volatile("ldmatrix.sync.aligned.m8n8.x4.shared.b16 {%0,%1,%2,%3}, [%4];"
                 : "=r"(r[0]), "=r"(r[1]), "=r"(r[2]), "=r"(r[3]) : "r"(addr));
}
__device__ __forceinline__ void ldsm4t(uint32_t* r, uint32_t addr) {
    asm volatile("ldmatrix.sync.aligned.m8n8.x4.trans.shared.b16 {%0,%1,%2,%3}, [%4];"
                 : "=r"(r[0]), "=r"(r[1]), "=r"(r[2]), "=r"(r[3]) : "r"(addr));
}
__device__ __forceinline__ void mma_f16(float* c, const uint32_t* a, const uint32_t* b) {
    asm volatile("mma.sync.aligned.m16n8k16.row.col.f32.f16.f16.f32 "
                 "{%0,%1,%2,%3},{%4,%5,%6,%7},{%8,%9},{%0,%1,%2,%3};"
                 : "+f"(c[0]), "+f"(c[1]), "+f"(c[2]), "+f"(c[3])
                 : "r"(a[0]), "r"(a[1]), "r"(a[2]), "r"(a[3]), "r"(b[0]), "r"(b[1]));
}

template<int TERMS, int NS>
__global__ __launch_bounds__(256, 2)
void mma_gemm(const __half* __restrict__ Ah, const __half* __restrict__ Al,
              const __half* __restrict__ Bh, const __half* __restrict__ Bl,
              float* __restrict__ C, int Kchunk,
              int lda, int ldb, int ldc,
              size_t slabStride,
              const float* __restrict__ bias)
{
    constexpr int NA = (TERMS >= 2) ? 2 : 1;
    constexpr int NB = (TERMS >= 3) ? 2 : 1;
    constexpr int AH_OFF = 0;
    constexpr int AL_OFF = A_PL;
    constexpr int BH_OFF = NA * A_PL;
    constexpr int BL_OFF = NA * A_PL + B_PL;
    constexpr uint32_t STAGE_B = (NA * A_PL + NB * B_PL) * 2;

    extern __shared__ __align__(16) char dynsmem[];

    const int tid  = threadIdx.x;
    const int lane = tid & 31;
    const int wid  = tid >> 5;
    const int wm   = (wid >> 2) * 64;
    const int wn   = (wid & 3) * 32;
    const int bm   = blockIdx.y * 128;
    const int bn   = blockIdx.x * 128;
    const int kb   = blockIdx.z * Kchunk;

    C += (size_t)blockIdx.z * slabStride;

    const uint32_t sbase = (uint32_t)__cvta_generic_to_shared(dynsmem);

    float acc[4][4][4];
#pragma unroll
    for (int i = 0; i < 4; i++)
#pragma unroll
        for (int j = 0; j < 4; j++)
#pragma unroll
            for (int k = 0; k < 4; k++) acc[i][j][k] = 0.f;

    const int KT = Kchunk >> 5;

    const __half* Ahb = Ah + (size_t)bm * lda + kb;
    const __half* Alb = (TERMS >= 2) ? (Al + (size_t)bm * lda + kb) : nullptr;
    const __half* Bhb = Bh + (size_t)kb * ldb + bn;
    const __half* Blb = (TERMS >= 3) ? (Bl + (size_t)kb * ldb + bn) : nullptr;

#define ISSUE(stage, kt_) {                                                    \
        uint32_t sb = sbase + (uint32_t)(stage) * STAGE_B;                     \
        int k0 = (kt_) << 5;                                                   \
        _Pragma("unroll")                                                      \
        for (int rep = 0; rep < 2; rep++) {                                    \
            int idx = rep * 256 + tid;                                         \
            int arw = idx >> 2,  acc_ = (idx & 3) * 8;                         \
            int brw = idx >> 4,  bcc_ = (idx & 15) * 8;                        \
            cp16(sb + (AH_OFF + arw * AS_ST + acc_) * 2,                       \
                 Ahb + (size_t)arw * lda + k0 + acc_);                         \
            if (TERMS >= 2)                                                    \
                cp16(sb + (AL_OFF + arw * AS_ST + acc_) * 2,                   \
                     Alb + (size_t)arw * lda + k0 + acc_);                     \
            cp16(sb + (BH_OFF + brw * BS_ST + bcc_) * 2,                       \
                 Bhb + (size_t)(k0 + brw) * ldb + bcc_);                       \
            if (TERMS >= 3)                                                    \
                cp16(sb + (BL_OFF + brw * BS_ST + bcc_) * 2,                   \
                     Blb + (size_t)(k0 + brw) * ldb + bcc_);                   \
        }                                                                      \
        asm volatile("cp.async.commit_group;\n");                              \
    }

    ISSUE(0, 0);
    if (NS >= 3 && KT > 1) ISSUE(1, 1);

    const int arow = lane & 15;
    const int acol = (lane >> 4) * 8;

    for (int kt = 0; kt < KT; ++kt) {
        if (NS >= 3 && kt + 1 < KT) asm volatile("cp.async.wait_group 1;\n");
        else                        asm volatile("cp.async.wait_group 0;\n");
        __syncthreads();

        if (NS >= 3) { if (kt + 2 < KT) ISSUE((kt + 2) % NS, kt + 2); }
        else         { if (kt + 1 < KT) ISSUE((kt + 1) & 1,  kt + 1); }

        uint32_t sb = sbase + (uint32_t)(kt % NS) * STAGE_B;

#pragma unroll
        for (int ks = 0; ks < 2; ks++) {
            const int kso = ks * 16;
            uint32_t ah[4][4], bx[4][2];
#pragma unroll
            for (int i = 0; i < 4; i++)
                ldsm4(ah[i], sb + (uint32_t)(AH_OFF + (wm + i * 16 + arow) * AS_ST + kso + acol) * 2);
#pragma unroll
            for (int jj = 0; jj < 2; jj++) {
                uint32_t r[4];
                ldsm4t(r, sb + (uint32_t)(BH_OFF + (kso + arow) * BS_ST + wn + jj * 16 + acol) * 2);
                bx[2 * jj][0] = r[0]; bx[2 * jj][1] = r[1];
                bx[2 * jj + 1][0] = r[2]; bx[2 * jj + 1][1] = r[3];
            }
#pragma unroll
            for (int i = 0; i < 4; i++)
#pragma unroll
                for (int j = 0; j < 4; j++) mma_f16(acc[i][j], ah[i], bx[j]);

            if (TERMS >= 2) {
                uint32_t al[4][4];
#pragma unroll
                for (int i = 0; i < 4; i++)
                    ldsm4(al[i], sb + (uint32_t)(AL_OFF + (wm + i * 16 + arow) * AS_ST + kso + acol) * 2);
#pragma unroll
                for (int i = 0; i < 4; i++)
#pragma unroll
                    for (int j = 0; j < 4; j++) mma_f16(acc[i][j], al[i], bx[j]);
            }
            if (TERMS >= 3) {
#pragma unroll
                for (int jj = 0; jj < 2; jj++) {
                    uint32_t r[4];
                    ldsm4t(r, sb + (uint32_t)(BL_OFF + (kso + arow) * BS_ST + wn + jj * 16 + acol) * 2);
                    bx[2 * jj][0] = r[0]; bx[2 * jj][1] = r[1];
                    bx[2 * jj + 1][0] = r[2]; bx[2 * jj + 1][1] = r[3];
                }
#pragma unroll
                for (int i = 0; i < 4; i++)
#pragma unroll
                    for (int j = 0; j < 4; j++) mma_f16(acc[i][j], ah[i], bx[j]);
            }
        }
    }
#undef ISSUE

    const bool sp = (bias != nullptr);
#pragma unroll
    for (int i = 0; i < 4; i++) {
        int row0 = bm + wm + i * 16 + (lane >> 2);
#pragma unroll
        for (int j = 0; j < 4; j++) {
            int col = bn + wn + j * 8 + (lane & 3) * 2;
            float v0 = acc[i][j][0], v1 = acc[i][j][1];
            float v2 = acc[i][j][2], v3 = acc[i][j][3];
            if (sp) {
                float b0 = bias[col], b1 = bias[col + 1];
                v0 += b0; v1 += b1; v2 += b0; v3 += b1;
                v0 = (v0 > 20.f) ? v0 : log1pf(__expf(v0));
                v1 = (v1 > 20.f) ? v1 : log1pf(__expf(v1));
                v2 = (v2 > 20.f) ? v2 : log1pf(__expf(v2));
                v3 = (v3 > 20.f) ? v3 : log1pf(__expf(v3));
            }
            *(float2*)(C + (size_t)row0 * ldc + col)       = make_float2(v0, v1);
            *(float2*)(C + (size_t)(row0 + 8) * ldc + col) = make_float2(v2, v3);
        }
    }
}

// ---------------------------------------------------------------------------
// Depthwise causal conv + bias + SiLU, vectorized x4 in d (bitwise-identical
// math to the scalar version; only change this round).
// ---------------------------------------------------------------------------
__global__ void conv_silu_kernel(const float* __restrict__ xz,
                                 const float* __restrict__ conv_w,
                                 const float* __restrict__ conv_b,
                                 float* __restrict__ xc,
                                 __half* __restrict__ xch,
                                 __half* __restrict__ xcl)
{
    int t = blockIdx.x * blockDim.x + threadIdx.x;       // 4 d-elems per thread
    if (t >= MROWS * DI / 4) return;
    int d4 = (t % (DI / 4)) * 4;
    int row = t / (DI / 4);
    int l = row & (LC - 1);
    int b = row >> 10;

    float4 acc = *(const float4*)(conv_b + d4);
#pragma unroll
    for (int jj = 0; jj < DCNV; jj++) {
        int ll = l + jj - (DCNV - 1);
        if (ll >= 0) {
            float4 xv = *(const float4*)(xz + (size_t)(b * LC + ll) * NXZ + d4);
            float w0 = conv_w[(d4 + 0) * DCNV + jj];
            float w1 = conv_w[(d4 + 1) * DCNV + jj];
            float w2 = conv_w[(d4 + 2) * DCNV + jj];
            float w3 = conv_w[(d4 + 3) * DCNV + jj];
            acc.x += xv.x * w0; acc.y += xv.y * w1;
            acc.z += xv.z * w2; acc.w += xv.w * w3;
        }
    }
    float4 v;
    v.x = acc.x / (1.f + __expf(-acc.x));
    v.y = acc.y / (1.f + __expf(-acc.y));
    v.z = acc.z / (1.f + __expf(-acc.z));
    v.w = acc.w / (1.f + __expf(-acc.w));

    size_t o = (size_t)row * DI + d4;
    *(float4*)(xc + o) = v;
    uint2 H, L; split4(v, H, L);
    *(uint2*)(xch + o) = H;
    *(uint2*)(xcl + o) = L;
}

// ---------------------------------------------------------------------------
// Selective scan (round-11 version): 8 lanes/channel, 2 states/lane,
// chunk-4 double buffering, 256-thread blocks. Emits y fp16 hi.
// ---------------------------------------------------------------------------
#define SCH 4
__global__ __launch_bounds__(256)
void scan_kernel(const float* __restrict__ dt,
                 const float* __restrict__ xc,
                 const float* __restrict__ dbl,
                 const float* __restrict__ xz,
                 const float* __restrict__ A_log,
                 const float* __restrict__ D_par,
                 __half* __restrict__ yh)
{
    const int gtid = blockIdx.x * 256 + threadIdx.x;
    const int ch = gtid >> 3;
    const int nl = gtid & 7;
    const int n0 = nl * 2;
    const int b  = ch >> 11;
    const int d  = ch & (DI - 1);

    const float An0 = -expf(A_log[d * DS + n0]);
    const float An1 = -expf(A_log[d * DS + n0 + 1]);
    const float Dv  = D_par[d];
    float h0 = 0.f, h1 = 0.f;

    const size_t rowbase = (size_t)b * LC;
    const float* pdt = dt  + rowbase * DI + d;
    const float* pxc = xc  + rowbase * DI + d;
    const float* pBC = dbl + rowbase * NDP + 64 + n0;
    const float* pz  = xz  + rowbase * NXZ + DI + d;
    __half* pyh = yh + rowbase * DI + d;

    float  dtb_[2][SCH], xcb[2][SCH], zb[2][SCH];
    float2 Bb[2][SCH], Cb[2][SCH];

#define LOADG(g_, p_) {                                                        \
        _Pragma("unroll")                                                      \
        for (int u = 0; u < SCH; u++) {                                        \
            size_t row = (size_t)((g_) * SCH + u);                             \
            dtb_[p_][u] = __ldg(pdt + row * DI);                               \
            xcb[p_][u]  = __ldg(pxc + row * DI);                               \
            Bb[p_][u]   = __ldg((const float2*)(pBC + row * NDP));             \
            Cb[p_][u]   = __ldg((const float2*)(pBC + row * NDP + DS));        \
            zb[p_][u]   = (nl == 0) ? __ldg(pz + row * NXZ) : 0.f;             \
        }                                                                      \
    }

    const int NG = LC / SCH;
    LOADG(0, 0);

#pragma unroll 2
    for (int g = 0; g < NG; g++) {
        const int p = g & 1;
        if (g + 1 < NG) LOADG(g + 1, p ^ 1);

#pragma unroll
        for (int u = 0; u < SCH; u++) {
            float dtv = dtb_[p][u], xcv = xcb[p][u];
            float2 Bv = Bb[p][u],   Cv  = Cb[p][u];

            float dx = dtv * xcv;
            h0 = __expf(dtv * An0) * h0 + dx * Bv.x;
            h1 = __expf(dtv * An1) * h1 + dx * Bv.y;

            float yv = h0 * Cv.x + h1 * Cv.y;
            yv += __shfl_xor_sync(0xffffffffu, yv, 4);
            yv += __shfl_xor_sync(0xffffffffu, yv, 2);
            yv += __shfl_xor_sync(0xffffffffu, yv, 1);

            if (nl == 0) {
                float zv  = zb[p][u];
                float sil = zv / (1.f + __expf(-zv));
                float yo  = (yv + xcv * Dv) * sil;
                pyh[(size_t)(g * SCH + u) * DI] = __float2half(yo);
            }
        }
    }
#undef LOADG
}

// ---------------------------------------------------------------------------
extern "C" void kernel_launch(void* const* d_in, const int* in_sizes, int n_in,
                              void* d_out, int out_size)
{
    const float* x      = (const float*)d_in[0];
    const float* W_in   = (const float*)d_in[1];
    const float* conv_w = (const float*)d_in[2];
    const float* conv_b = (const float*)d_in[3];
    const float* W_x    = (const float*)d_in[4];
    const float* W_dt   = (const float*)d_in[5];
    const float* b_dt   = (const float*)d_in[6];
    const float* A_log  = (const float*)d_in[7];
    const float* D_par  = (const float*)d_in[8];
    const float* W_out  = (const float*)d_in[9];
    float* out = (float*)d_out;

    float *xz, *xc, *dtb, *dbl, *dblp, *osp;
    __half *xh, *Wih, *Wxh, *Wxl, *xch, *xcl,
           *dbh, *dbll, *Wdh, *Wdl, *yh, *Woh;
    cudaGetSymbolAddress((void**)&xz,   g_xz);
    cudaGetSymbolAddress((void**)&xc,   g_xc);
    cudaGetSymbolAddress((void**)&dtb,  g_dt);
    cudaGetSymbolAddress((void**)&dbl,  g_dbl);
    cudaGetSymbolAddress((void**)&dblp, g_dblp);
    cudaGetSymbolAddress((void**)&osp,  g_osp);
    cudaGetSymbolAddress((void**)&xh,   g_xh);
    cudaGetSymbolAddress((void**)&Wih,  g_Wih);
    cudaGetSymbolAddress((void**)&Wxh,  g_Wxh);  cudaGetSymbolAddress((void**)&Wxl,  g_Wxl);
    cudaGetSymbolAddress((void**)&xch,  g_xch);  cudaGetSymbolAddress((void**)&xcl,  g_xcl);
    cudaGetSymbolAddress((void**)&dbh,  g_dbh);  cudaGetSymbolAddress((void**)&dbll, g_dbll);
    cudaGetSymbolAddress((void**)&Wdh,  g_Wdh);  cudaGetSymbolAddress((void**)&Wdl,  g_Wdl);
    cudaGetSymbolAddress((void**)&yh,   g_yh);
    cudaGetSymbolAddress((void**)&Woh,  g_Woh);

    const int SMEM1 = 3 * (1 * A_PL + 1 * B_PL) * 2;
    const int SMEM3 = 2 * (2 * A_PL + 2 * B_PL) * 2;
    cudaFuncSetAttribute((const void*)mma_gemm<1, 3>,
                         cudaFuncAttributeMaxDynamicSharedMemorySize, SMEM1);
    cudaFuncSetAttribute((const void*)mma_gemm<3, 2>,
                         cudaFuncAttributeMaxDynamicSharedMemorySize, SMEM3);

    // 0) all input conversions (one kernel)
    prep_kernel<<<(SEG5 + 255) / 256, 256>>>(
        (const float4*)x, (const float4*)W_in, (const float4*)W_dt,
        (const float4*)W_out, W_x,
        (uint2*)xh, (uint2*)Wih,
        (uint2*)Wdh, (uint2*)Wdl, (uint2*)Woh, (uint2*)Wxh, (uint2*)Wxl);

    // 1) xz = x @ W_in (1-term)
    mma_gemm<1, 3><<<dim3(NXZ / 128, MROWS / 128, 1), 256, SMEM1>>>(
        xh, nullptr, Wih, nullptr, xz, DM, DM, NXZ, NXZ, 0, nullptr);

    // 2) conv + SiLU (+ fp16 split), vectorized x4 (only change this round)
    conv_silu_kernel<<<(MROWS * DI / 4 + 255) / 256, 256>>>(
        xz, conv_w, conv_b, xc, xch, xcl);

    // 3) dbl = xc @ W_x_padded (3-term), K-split 8
    mma_gemm<3, 2><<<dim3(1, MROWS / 128, 8), 256, SMEM3>>>(
        xch, xcl, Wxh, Wxl, dblp, DI / 8, DI, NDP, NDP,
        (size_t)MROWS * NDP, nullptr);

    // 4) reduce partials + compact fp16 of dt-rank slice
    reduce_dbl_kernel<<<(MROWS * NDP + 255) / 256, 256>>>(dblp, dbl, dbh, dbll);

    // 5) dt = softplus(dbl[:,:64] @ W_dt + b_dt) (3-term)
    mma_gemm<3, 2><<<dim3(DI / 128, MROWS / 128, 1), 256, SMEM3>>>(
        dbh, dbll, Wdh, Wdl, dtb, DTR, DTR, DI, DI, 0, b_dt);

    // 6) selective scan -> y (fp16 hi)
    scan_kernel<<<(BC * DI * 8) / 256, 256>>>(dtb, xc, dbl, xz, A_log, D_par, yh);

    // 7) out = y @ W_out (1-term), K-split 2 -> slabs
    mma_gemm<1, 3><<<dim3(DM / 128, MROWS / 128, 2), 256, SMEM1>>>(
        yh, nullptr, Woh, nullptr, osp, DI / 2, DI, DM, DM,
        (size_t)MROWS * DM, nullptr);

    // 8) out = slab0 + slab1
    reduce_out_kernel<<<(MROWS * DM / 4 + 255) / 256, 256>>>(
        (const float4*)osp, (const float4*)(osp + (size_t)MROWS * DM),
        (float4*)out, MROWS * DM / 4);
}

// round 14
// speedup vs baseline: 1.0595x; 1.0595x over previous
#include <cuda_runtime.h>
#include <cuda_fp16.h>
#include <cstdint>

// Problem dims (fixed)
#define BC   2
#define LC   1024
#define DM   1024
#define DI   2048
#define DS   16
#define DCNV 4
#define DTR  64
#define MROWS (BC*LC)      // 2048
#define NXZ   (2*DI)       // 4096
#define NDP   128

// ---------------- scratch (device globals) ----------------
__device__ float g_xz  [MROWS * NXZ];
__device__ float g_xc  [MROWS * DI];
__device__ float g_dt  [MROWS * DI];
__device__ float g_dbl [MROWS * NDP];
__device__ float g_dblp[8 * MROWS * NDP];
__device__ float g_osp [2 * MROWS * DM];

__device__ __half g_xh  [MROWS * DM];
__device__ __half g_Wih [DM * NXZ];
__device__ __half g_Wxh [DI * NDP],    g_Wxl [DI * NDP];
__device__ __half g_xch [MROWS * DI],  g_xcl [MROWS * DI];
__device__ __half g_dbh [MROWS * DTR], g_dbll[MROWS * DTR];
__device__ __half g_Wdh [DTR * DI],    g_Wdl [DTR * DI];
__device__ __half g_yh  [MROWS * DI];
__device__ __half g_Woh [DI * DM];

// ---------------------------------------------------------------------------
// helpers
// ---------------------------------------------------------------------------
__device__ __forceinline__ uint32_t pack_h2(float a, float b) {
    __half2 h = __floats2half2_rn(a, b);
    return *reinterpret_cast<uint32_t*>(&h);
}
__device__ __forceinline__ void split4(float4 v, uint2& H, uint2& L) {
    float hx = __half2float(__float2half(v.x));
    float hy = __half2float(__float2half(v.y));
    float hz = __half2float(__float2half(v.z));
    float hw = __half2float(__float2half(v.w));
    H.x = pack_h2(v.x, v.y);            H.y = pack_h2(v.z, v.w);
    L.x = pack_h2(v.x - hx, v.y - hy);  L.y = pack_h2(v.z - hz, v.w - hw);
}

// ---------------------------------------------------------------------------
// Fused conversion, ILP x4 (measured-positive with scan-128 pair).
// Segments (float4 units):
//   [0,SEG1): x -> xh (hi)             [SEG1,SEG2): W_in -> Wih (hi)
//   [SEG2,SEG3): W_dt -> hi/lo         [SEG3,SEG4): W_out -> Woh (hi)
//   [SEG4,SEG5): W_x -> hi/lo padded [DI x 128]
// ---------------------------------------------------------------------------
#define SEG1  524288
#define SEG2 1572864
#define SEG3 1605632
#define SEG4 2129920
#define SEG5 2195456

__device__ __forceinline__ const float4* seg_src(
    int i, const float4* x, const float4* W_in, const float4* W_dt,
    const float4* W_out, const float* W_x, int& kind, int& j)
{
    if (i < SEG1)      { kind = 0; j = i;        return x + j; }
    else if (i < SEG2) { kind = 1; j = i - SEG1; return W_in + j; }
    else if (i < SEG3) { kind = 2; j = i - SEG2; return W_dt + j; }
    else if (i < SEG4) { kind = 3; j = i - SEG3; return W_out + j; }
    kind = 4; j = i - SEG4;
    int idx = j * 4;
    int r = idx >> 7, c = idx & 127;
    return (c < 96) ? (const float4*)(W_x + (size_t)r * 96 + c) : nullptr;
}

__global__ void prep_kernel(const float4* __restrict__ x,
                            const float4* __restrict__ W_in,
                            const float4* __restrict__ W_dt,
                            const float4* __restrict__ W_out,
                            const float*  __restrict__ W_x,
                            uint2* __restrict__ xh,
                            uint2* __restrict__ Wih,
                            uint2* __restrict__ Wdh, uint2* __restrict__ Wdl,
                            uint2* __restrict__ Woh,
                            uint2* __restrict__ Wxh, uint2* __restrict__ Wxl)
{
    int base = (blockIdx.x * blockDim.x) * 4 + threadIdx.x;
    float4 v[4];
    int kind[4], j[4];
    bool ok[4];
#pragma unroll
    for (int u = 0; u < 4; u++) {
        int i = base + u * blockDim.x;
        ok[u] = (i < SEG5);
        if (ok[u]) {
            const float4* p = seg_src(i, x, W_in, W_dt, W_out, W_x, kind[u], j[u]);
            v[u] = p ? __ldg(p) : make_float4(0.f, 0.f, 0.f, 0.f);
        }
    }
#pragma unroll
    for (int u = 0; u < 4; u++) {
        if (!ok[u]) continue;
        if (kind[u] == 0) {
            uint2 H; H.x = pack_h2(v[u].x, v[u].y); H.y = pack_h2(v[u].z, v[u].w);
            xh[j[u]] = H;
        } else if (kind[u] == 1) {
            uint2 H; H.x = pack_h2(v[u].x, v[u].y); H.y = pack_h2(v[u].z, v[u].w);
            Wih[j[u]] = H;
        } else if (kind[u] == 2) {
            uint2 H, L; split4(v[u], H, L);
            Wdh[j[u]] = H; Wdl[j[u]] = L;
        } else if (kind[u] == 3) {
            uint2 H; H.x = pack_h2(v[u].x, v[u].y); H.y = pack_h2(v[u].z, v[u].w);
            Woh[j[u]] = H;
        } else {
            uint2 H, L; split4(v[u], H, L);
            Wxh[j[u]] = H; Wxl[j[u]] = L;
        }
    }
}

// ---------------------------------------------------------------------------
// reduces
// ---------------------------------------------------------------------------
__global__ void reduce_dbl_kernel(const float* __restrict__ parts,
                                  float* __restrict__ dbl,
                                  __half* __restrict__ dbh,
                                  __half* __restrict__ dbll)
{
    int i = blockIdx.x * blockDim.x + threadIdx.x;
    if (i >= MROWS * NDP) return;
    float s = 0.f;
#pragma unroll
    for (int k = 0; k < 8; k++) s += parts[(size_t)k * MROWS * NDP + i];
    dbl[i] = s;
    int c = i & 127;
    if (c < 64) {
        int r = i >> 7;
        __half h = __float2half(s);
        dbh [r * DTR + c] = h;
        dbll[r * DTR + c] = __float2half(s - __half2float(h));
    }
}

__global__ void reduce_out_kernel(const float4* __restrict__ s0,
                                  const float4* __restrict__ s1,
                                  float4* __restrict__ out, int n4)
{
    int i = blockIdx.x * blockDim.x + threadIdx.x;
    if (i >= n4) return;
    float4 a = s0[i], b = s1[i];
    out[i] = make_float4(a.x + b.x, a.y + b.y, a.z + b.z, a.w + b.w);
}

// ---------------------------------------------------------------------------
// Tensor-core GEMM: 128x128 CTA, 256 threads (8 warps, 64x32 warp tile).
// TERMS = 1 (AhBh), 2 (+AlBh), 3 (+AhBl). BK=32, NS-stage cp.async.
// ---------------------------------------------------------------------------
#define AS_ST 40
#define BS_ST 136
#define A_PL  (128*AS_ST)
#define B_PL  (32*BS_ST)

__device__ __forceinline__ void cp16(uint32_t dst, const void* src) {
    asm volatile("cp.async.cg.shared.global [%0], [%1], 16;\n" :: "r"(dst), "l"(src));
}
__device__ __forceinline__ void ldsm4(uint32_t* r, uint32_t addr) {
    asm volatile("ldmatrix.sync.aligned.m8n8.x4.shared.b16 {%0,%1,%2,%3}, [%4];"
                 : "=r"(r[0]), "=r"(r[1]), "=r"(r[2]), "=r"(r[3]) : "r"(addr));
}
__device__ __forceinline__ void ldsm4t(uint32_t* r, uint32_t addr) {
    asm volatile("ldmatrix.sync.aligned.m8n8.x4.trans.shared.b16 {%0,%1,%2,%3}, [%4];"
                 : "=r"(r[0]), "=r"(r[1]), "=r"(r[2]), "=r"(r[3]) : "r"(addr));
}
__device__ __forceinline__ void mma_f16(float* c, const uint32_t* a, const uint32_t* b) {
    asm volatile("mma.sync.aligned.m16n8k16.row.col.f32.f16.f16.f32 "
                 "{%0,%1,%2,%3},{%4,%5,%6,%7},{%8,%9},{%0,%1,%2,%3};"
                 : "+f"(c[0]), "+f"(c[1]), "+f"(c[2]), "+f"(c[3])
                 : "r"(a[0]), "r"(a[1]), "r"(a[2]), "r"(a[3]), "r"(b[0]), "r"(b[1]));
}

template<int TERMS, int NS>
__global__ __launch_bounds__(256, 2)
void mma_gemm(const __half* __restrict__ Ah, const __half* __restrict__ Al,
              const __half* __restrict__ Bh, const __half* __restrict__ Bl,
              float* __restrict__ C, int Kchunk,
              int lda, int ldb, int ldc,
              size_t slabStride,
              const float* __restrict__ bias)
{
    constexpr int NA = (TERMS >= 2) ? 2 : 1;
    constexpr int NB = (TERMS >= 3) ? 2 : 1;
    constexpr int AH_OFF = 0;
    constexpr int AL_OFF = A_PL;
    constexpr int BH_OFF = NA * A_PL;
    constexpr int BL_OFF = NA * A_PL + B_PL;
    constexpr uint32_t STAGE_B = (NA * A_PL + NB * B_PL) * 2;

    extern __shared__ __align__(16) char dynsmem[];

    const int tid  = threadIdx.x;
    const int lane = tid & 31;
    const int wid  = tid >> 5;
    const int wm   = (wid >> 2) * 64;
    const int wn   = (wid & 3) * 32;
    const int bm   = blockIdx.y * 128;
    const int bn   = blockIdx.x * 128;
    const int kb   = blockIdx.z * Kchunk;

    C += (size_t)blockIdx.z * slabStride;

    const uint32_t sbase = (uint32_t)__cvta_generic_to_shared(dynsmem);

    float acc[4][4][4];
#pragma unroll
    for (int i = 0; i < 4; i++)
#pragma unroll
        for (int j = 0; j < 4; j++)
#pragma unroll
            for (int k = 0; k < 4; k++) acc[i][j][k] = 0.f;

    const int KT = Kchunk >> 5;

    const __half* Ahb = Ah + (size_t)bm * lda + kb;
    const __half* Alb = (TERMS >= 2) ? (Al + (size_t)bm * lda + kb) : nullptr;
    const __half* Bhb = Bh + (size_t)kb * ldb + bn;
    const __half* Blb = (TERMS >= 3) ? (Bl + (size_t)kb * ldb + bn) : nullptr;

#define ISSUE(stage, kt_) {                                                    \
        uint32_t sb = sbase + (uint32_t)(stage) * STAGE_B;                     \
        int k0 = (kt_) << 5;                                                   \
        _Pragma("unroll")                                                      \
        for (int rep = 0; rep < 2; rep++) {                                    \
            int idx = rep * 256 + tid;                                         \
            int arw = idx >> 2,  acc_ = (idx & 3) * 8;                         \
            int brw = idx >> 4,  bcc_ = (idx & 15) * 8;                        \
            cp16(sb + (AH_OFF + arw * AS_ST + acc_) * 2,                       \
                 Ahb + (size_t)arw * lda + k0 + acc_);                         \
            if (TERMS >= 2)                                                    \
                cp16(sb + (AL_OFF + arw * AS_ST + acc_) * 2,                   \
                     Alb + (size_t)arw * lda + k0 + acc_);                     \
            cp16(sb + (BH_OFF + brw * BS_ST + bcc_) * 2,                       \
                 Bhb + (size_t)(k0 + brw) * ldb + bcc_);                       \
            if (TERMS >= 3)                                                    \
                cp16(sb + (BL_OFF + brw * BS_ST + bcc_) * 2,                   \
                     Blb + (size_t)(k0 + brw) * ldb + bcc_);                   \
        }                                                                      \
        asm volatile("cp.async.commit_group;\n");                              \
    }

    ISSUE(0, 0);
    if (NS >= 3 && KT > 1) ISSUE(1, 1);

    const int arow = lane & 15;
    const int acol = (lane >> 4) * 8;

    for (int kt = 0; kt < KT; ++kt) {
        if (NS >= 3 && kt + 1 < KT) asm volatile("cp.async.wait_group 1;\n");
        else                        asm volatile("cp.async.wait_group 0;\n");
        __syncthreads();

        if (NS >= 3) { if (kt + 2 < KT) ISSUE((kt + 2) % NS, kt + 2); }
        else         { if (kt + 1 < KT) ISSUE((kt + 1) & 1,  kt + 1); }

        uint32_t sb = sbase + (uint32_t)(kt % NS) * STAGE_B;

#pragma unroll
        for (int ks = 0; ks < 2; ks++) {
            const int kso = ks * 16;
            uint32_t ah[4][4], bx[4][2];
#pragma unroll
            for (int i = 0; i < 4; i++)
                ldsm4(ah[i], sb + (uint32_t)(AH_OFF + (wm + i * 16 + arow) * AS_ST + kso + acol) * 2);
#pragma unroll
            for (int jj = 0; jj < 2; jj++) {
                uint32_t r[4];
                ldsm4t(r, sb + (uint32_t)(BH_OFF + (kso + arow) * BS_ST + wn + jj * 16 + acol) * 2);
                bx[2 * jj][0] = r[0]; bx[2 * jj][1] = r[1];
                bx[2 * jj + 1][0] = r[2]; bx[2 * jj + 1][1] = r[3];
            }
#pragma unroll
            for (int i = 0; i < 4; i++)
#pragma unroll
                for (int j = 0; j < 4; j++) mma_f16(acc[i][j], ah[i], bx[j]);

            if (TERMS >= 2) {
                uint32_t al[4][4];
#pragma unroll
                for (int i = 0; i < 4; i++)
                    ldsm4(al[i], sb + (uint32_t)(AL_OFF + (wm + i * 16 + arow) * AS_ST + kso + acol) * 2);
#pragma unroll
                for (int i = 0; i < 4; i++)
#pragma unroll
                    for (int j = 0; j < 4; j++) mma_f16(acc[i][j], al[i], bx[j]);
            }
            if (TERMS >= 3) {
#pragma unroll
                for (int jj = 0; jj < 2; jj++) {
                    uint32_t r[4];
                    ldsm4t(r, sb + (uint32_t)(BL_OFF + (kso + arow) * BS_ST + wn + jj * 16 + acol) * 2);
                    bx[2 * jj][0] = r[0]; bx[2 * jj][1] = r[1];
                    bx[2 * jj + 1][0] = r[2]; bx[2 * jj + 1][1] = r[3];
                }
#pragma unroll
                for (int i = 0; i < 4; i++)
#pragma unroll
                    for (int j = 0; j < 4; j++) mma_f16(acc[i][j], ah[i], bx[j]);
            }
        }
    }
#undef ISSUE

    const bool sp = (bias != nullptr);
#pragma unroll
    for (int i = 0; i < 4; i++) {
        int row0 = bm + wm + i * 16 + (lane >> 2);
#pragma unroll
        for (int j = 0; j < 4; j++) {
            int col = bn + wn + j * 8 + (lane & 3) * 2;
            float v0 = acc[i][j][0], v1 = acc[i][j][1];
            float v2 = acc[i][j][2], v3 = acc[i][j][3];
            if (sp) {
                float b0 = bias[col], b1 = bias[col + 1];
                v0 += b0; v1 += b1; v2 += b0; v3 += b1;
                v0 = (v0 > 20.f) ? v0 : log1pf(__expf(v0));
                v1 = (v1 > 20.f) ? v1 : log1pf(__expf(v1));
                v2 = (v2 > 20.f) ? v2 : log1pf(__expf(v2));
                v3 = (v3 > 20.f) ? v3 : log1pf(__expf(v3));
            }
            *(float2*)(C + (size_t)row0 * ldc + col)       = make_float2(v0, v1);
            *(float2*)(C + (size_t)(row0 + 8) * ldc + col) = make_float2(v2, v3);
        }
    }
}

// ---------------------------------------------------------------------------
// Depthwise causal conv (width 4) + bias + SiLU — round-11 SCALAR version
// (measured fastest; the x4 variant regressed).
// ---------------------------------------------------------------------------
__global__ void conv_silu_kernel(const float* __restrict__ xz,
                                 const float* __restrict__ conv_w,
                                 const float* __restrict__ conv_b,
                                 float* __restrict__ xc,
                                 __half* __restrict__ xch,
                                 __half* __restrict__ xcl)
{
    int idx = blockIdx.x * blockDim.x + threadIdx.x;
    if (idx >= MROWS * DI) return;
    int d = idx & (DI - 1);
    int l = (idx >> 11) & (LC - 1);
    int b = idx >> 21;

    float acc = conv_b[d];
#pragma unroll
    for (int j = 0; j < DCNV; j++) {
        int ll = l + j - (DCNV - 1);
        if (ll >= 0)
            acc += xz[(size_t)(b * LC + ll) * NXZ + d] * conv_w[d * DCNV + j];
    }
    float v = acc / (1.f + __expf(-acc));
    xc[idx] = v;
    __half h = __float2half(v);
    xch[idx] = h;
    xcl[idx] = __float2half(v - __half2float(h));
}

// ---------------------------------------------------------------------------
// Selective scan: 8 lanes/channel, 2 states/lane, chunk-4 double buffering.
// 128-thread blocks (256 CTAs over 148 SMs).
// ---------------------------------------------------------------------------
#define SCH 4
__global__ __launch_bounds__(128)
void scan_kernel(const float* __restrict__ dt,
                 const float* __restrict__ xc,
                 const float* __restrict__ dbl,
                 const float* __restrict__ xz,
                 const float* __restrict__ A_log,
                 const float* __restrict__ D_par,
                 __half* __restrict__ yh)
{
    const int gtid = blockIdx.x * 128 + threadIdx.x;
    const int ch = gtid >> 3;
    const int nl = gtid & 7;
    const int n0 = nl * 2;
    const int b  = ch >> 11;
    const int d  = ch & (DI - 1);

    const float An0 = -expf(A_log[d * DS + n0]);
    const float An1 = -expf(A_log[d * DS + n0 + 1]);
    const float Dv  = D_par[d];
    float h0 = 0.f, h1 = 0.f;

    const size_t rowbase = (size_t)b * LC;
    const float* pdt = dt  + rowbase * DI + d;
    const float* pxc = xc  + rowbase * DI + d;
    const float* pBC = dbl + rowbase * NDP + 64 + n0;
    const float* pz  = xz  + rowbase * NXZ + DI + d;
    __half* pyh = yh + rowbase * DI + d;

    float  dtb_[2][SCH], xcb[2][SCH], zb[2][SCH];
    float2 Bb[2][SCH], Cb[2][SCH];

#define LOADG(g_, p_) {                                                        \
        _Pragma("unroll")                                                      \
        for (int u = 0; u < SCH; u++) {                                        \
            size_t row = (size_t)((g_) * SCH + u);                             \
            dtb_[p_][u] = __ldg(pdt + row * DI);                               \
            xcb[p_][u]  = __ldg(pxc + row * DI);                               \
            Bb[p_][u]   = __ldg((const float2*)(pBC + row * NDP));             \
            Cb[p_][u]   = __ldg((const float2*)(pBC + row * NDP + DS));        \
            zb[p_][u]   = (nl == 0) ? __ldg(pz + row * NXZ) : 0.f;             \
        }                                                                      \
    }

    const int NG = LC / SCH;
    LOADG(0, 0);

#pragma unroll 2
    for (int g = 0; g < NG; g++) {
        const int p = g & 1;
        if (g + 1 < NG) LOADG(g + 1, p ^ 1);

#pragma unroll
        for (int u = 0; u < SCH; u++) {
            float dtv = dtb_[p][u], xcv = xcb[p][u];
            float2 Bv = Bb[p][u],   Cv  = Cb[p][u];

            float dx = dtv * xcv;
            h0 = __expf(dtv * An0) * h0 + dx * Bv.x;
            h1 = __expf(dtv * An1) * h1 + dx * Bv.y;

            float yv = h0 * Cv.x + h1 * Cv.y;
            yv += __shfl_xor_sync(0xffffffffu, yv, 4);
            yv += __shfl_xor_sync(0xffffffffu, yv, 2);
            yv += __shfl_xor_sync(0xffffffffu, yv, 1);

            if (nl == 0) {
                float zv  = zb[p][u];
                float sil = zv / (1.f + __expf(-zv));
                float yo  = (yv + xcv * Dv) * sil;
                pyh[(size_t)(g * SCH + u) * DI] = __float2half(yo);
            }
        }
    }
#undef LOADG
}

// ---------------------------------------------------------------------------
extern "C" void kernel_launch(void* const* d_in, const int* in_sizes, int n_in,
                              void* d_out, int out_size)
{
    const float* x      = (const float*)d_in[0];
    const float* W_in   = (const float*)d_in[1];
    const float* conv_w = (const float*)d_in[2];
    const float* conv_b = (const float*)d_in[3];
    const float* W_x    = (const float*)d_in[4];
    const float* W_dt   = (const float*)d_in[5];
    const float* b_dt   = (const float*)d_in[6];
    const float* A_log  = (const float*)d_in[7];
    const float* D_par  = (const float*)d_in[8];
    const float* W_out  = (const float*)d_in[9];
    float* out = (float*)d_out;

    float *xz, *xc, *dtb, *dbl, *dblp, *osp;
    __half *xh, *Wih, *Wxh, *Wxl, *xch, *xcl,
           *dbh, *dbll, *Wdh, *Wdl, *yh, *Woh;
    cudaGetSymbolAddress((void**)&xz,   g_xz);
    cudaGetSymbolAddress((void**)&xc,   g_xc);
    cudaGetSymbolAddress((void**)&dtb,  g_dt);
    cudaGetSymbolAddress((void**)&dbl,  g_dbl);
    cudaGetSymbolAddress((void**)&dblp, g_dblp);
    cudaGetSymbolAddress((void**)&osp,  g_osp);
    cudaGetSymbolAddress((void**)&xh,   g_xh);
    cudaGetSymbolAddress((void**)&Wih,  g_Wih);
    cudaGetSymbolAddress((void**)&Wxh,  g_Wxh);  cudaGetSymbolAddress((void**)&Wxl,  g_Wxl);
    cudaGetSymbolAddress((void**)&xch,  g_xch);  cudaGetSymbolAddress((void**)&xcl,  g_xcl);
    cudaGetSymbolAddress((void**)&dbh,  g_dbh);  cudaGetSymbolAddress((void**)&dbll, g_dbll);
    cudaGetSymbolAddress((void**)&Wdh,  g_Wdh);  cudaGetSymbolAddress((void**)&Wdl,  g_Wdl);
    cudaGetSymbolAddress((void**)&yh,   g_yh);
    cudaGetSymbolAddress((void**)&Woh,  g_Woh);

    const int SMEM1 = 3 * (1 * A_PL + 1 * B_PL) * 2;
    const int SMEM3 = 2 * (2 * A_PL + 2 * B_PL) * 2;
    cudaFuncSetAttribute((const void*)mma_gemm<1, 3>,
                         cudaFuncAttributeMaxDynamicSharedMemorySize, SMEM1);
    cudaFuncSetAttribute((const void*)mma_gemm<3, 2>,
                         cudaFuncAttributeMaxDynamicSharedMemorySize, SMEM3);

    // 0) all input conversions (ILP x4)
    prep_kernel<<<(SEG5 + 1023) / 1024, 256>>>(
        (const float4*)x, (const float4*)W_in, (const float4*)W_dt,
        (const float4*)W_out, W_x,
        (uint2*)xh, (uint2*)Wih,
        (uint2*)Wdh, (uint2*)Wdl, (uint2*)Woh, (uint2*)Wxh, (uint2*)Wxl);

    // 1) xz = x @ W_in (1-term)
    mma_gemm<1, 3><<<dim3(NXZ / 128, MROWS / 128, 1), 256, SMEM1>>>(
        xh, nullptr, Wih, nullptr, xz, DM, DM, NXZ, NXZ, 0, nullptr);

    // 2) conv + SiLU (+ fp16 split), scalar (round-11 measured-best)
    conv_silu_kernel<<<(MROWS * DI) / 256, 256>>>(xz, conv_w, conv_b, xc, xch, xcl);

    // 3) dbl = xc @ W_x_padded (3-term), K-split 8
    mma_gemm<3, 2><<<dim3(1, MROWS / 128, 8), 256, SMEM3>>>(
        xch, xcl, Wxh, Wxl, dblp, DI / 8, DI, NDP, NDP,
        (size_t)MROWS * NDP, nullptr);

    // 4) reduce partials + compact fp16 of dt-rank slice
    reduce_dbl_kernel<<<(MROWS * NDP + 255) / 256, 256>>>(dblp, dbl, dbh, dbll);

    // 5) dt = softplus(dbl[:,:64] @ W_dt + b_dt) (3-term)
    mma_gemm<3, 2><<<dim3(DI / 128, MROWS / 128, 1), 256, SMEM3>>>(
        dbh, dbll, Wdh, Wdl, dtb, DTR, DTR, DI, DI, 0, b_dt);

    // 6) selective scan -> y (fp16 hi), 128-thread blocks
    scan_kernel<<<(BC * DI * 8) / 128, 128>>>(dtb, xc, dbl, xz, A_log, D_par, yh);

    // 7) out = y @ W_out (1-term), K-split 2 -> slabs
    mma_gemm<1, 3><<<dim3(DM / 128, MROWS / 128, 2), 256, SMEM1>>>(
        yh, nullptr, Woh, nullptr, osp, DI / 2, DI, DM, DM,
        (size_t)MROWS * DM, nullptr);

    // 8) out = slab0 + slab1
    reduce_out_kernel<<<(MROWS * DM / 4 + 255) / 256, 256>>>(
        (const float4*)osp, (const float4*)(osp + (size_t)MROWS * DM),
        (float4*)out, MROWS * DM / 4);
}

// round 15
// speedup vs baseline: 1.0915x; 1.0302x over previous
#include <cuda_runtime.h>
#include <cuda_fp16.h>
#include <cstdint>

// Problem dims (fixed)
#define BC   2
#define LC   1024
#define DM   1024
#define DI   2048
#define DS   16
#define DCNV 4
#define DTR  64
#define MROWS (BC*LC)      // 2048
#define NXZ   (2*DI)       // 4096
#define NDP   128

// ---------------- scratch (device globals) ----------------
__device__ float g_xz  [MROWS * NXZ];
__device__ float g_xc  [MROWS * DI];
__device__ float g_dt  [MROWS * DI];
__device__ float g_dbl [MROWS * NDP];
__device__ float g_dblp[8 * MROWS * NDP];
__device__ float g_osp [2 * MROWS * DM];

__device__ __half g_xh  [MROWS * DM];
__device__ __half g_Wih [DM * NXZ];
__device__ __half g_Wxh [DI * NDP],    g_Wxl [DI * NDP];
__device__ __half g_xch [MROWS * DI],  g_xcl [MROWS * DI];
__device__ __half g_dbh [MROWS * DTR], g_dbll[MROWS * DTR];
__device__ __half g_Wdh [DTR * DI],    g_Wdl [DTR * DI];
__device__ __half g_yh  [MROWS * DI];
__device__ __half g_Woh [DI * DM];

// ---------------------------------------------------------------------------
// helpers
// ---------------------------------------------------------------------------
__device__ __forceinline__ uint32_t pack_h2(float a, float b) {
    __half2 h = __floats2half2_rn(a, b);
    return *reinterpret_cast<uint32_t*>(&h);
}
__device__ __forceinline__ void split4(float4 v, uint2& H, uint2& L) {
    float hx = __half2float(__float2half(v.x));
    float hy = __half2float(__float2half(v.y));
    float hz = __half2float(__float2half(v.z));
    float hw = __half2float(__float2half(v.w));
    H.x = pack_h2(v.x, v.y);            H.y = pack_h2(v.z, v.w);
    L.x = pack_h2(v.x - hx, v.y - hy);  L.y = pack_h2(v.z - hz, v.w - hw);
}

// ---------------------------------------------------------------------------
// Fused conversion, ILP x4 (round-14 measured-best). Segments (float4 units):
//   [0,SEG1): x -> xh (hi)             [SEG1,SEG2): W_in -> Wih (hi)
//   [SEG2,SEG3): W_dt -> hi/lo         [SEG3,SEG4): W_out -> Woh (hi)
//   [SEG4,SEG5): W_x -> hi/lo padded [DI x 128]
// ---------------------------------------------------------------------------
#define SEG1  524288
#define SEG2 1572864
#define SEG3 1605632
#define SEG4 2129920
#define SEG5 2195456

__device__ __forceinline__ const float4* seg_src(
    int i, const float4* x, const float4* W_in, const float4* W_dt,
    const float4* W_out, const float* W_x, int& kind, int& j)
{
    if (i < SEG1)      { kind = 0; j = i;        return x + j; }
    else if (i < SEG2) { kind = 1; j = i - SEG1; return W_in + j; }
    else if (i < SEG3) { kind = 2; j = i - SEG2; return W_dt + j; }
    else if (i < SEG4) { kind = 3; j = i - SEG3; return W_out + j; }
    kind = 4; j = i - SEG4;
    int idx = j * 4;
    int r = idx >> 7, c = idx & 127;
    return (c < 96) ? (const float4*)(W_x + (size_t)r * 96 + c) : nullptr;
}

__global__ void prep_kernel(const float4* __restrict__ x,
                            const float4* __restrict__ W_in,
                            const float4* __restrict__ W_dt,
                            const float4* __restrict__ W_out,
                            const float*  __restrict__ W_x,
                            uint2* __restrict__ xh,
                            uint2* __restrict__ Wih,
                            uint2* __restrict__ Wdh, uint2* __restrict__ Wdl,
                            uint2* __restrict__ Woh,
                            uint2* __restrict__ Wxh, uint2* __restrict__ Wxl)
{
    int base = (blockIdx.x * blockDim.x) * 4 + threadIdx.x;
    float4 v[4];
    int kind[4], j[4];
    bool ok[4];
#pragma unroll
    for (int u = 0; u < 4; u++) {
        int i = base + u * blockDim.x;
        ok[u] = (i < SEG5);
        if (ok[u]) {
            const float4* p = seg_src(i, x, W_in, W_dt, W_out, W_x, kind[u], j[u]);
            v[u] = p ? __ldg(p) : make_float4(0.f, 0.f, 0.f, 0.f);
        }
    }
#pragma unroll
    for (int u = 0; u < 4; u++) {
        if (!ok[u]) continue;
        if (kind[u] == 0) {
            uint2 H; H.x = pack_h2(v[u].x, v[u].y); H.y = pack_h2(v[u].z, v[u].w);
            xh[j[u]] = H;
        } else if (kind[u] == 1) {
            uint2 H; H.x = pack_h2(v[u].x, v[u].y); H.y = pack_h2(v[u].z, v[u].w);
            Wih[j[u]] = H;
        } else if (kind[u] == 2) {
            uint2 H, L; split4(v[u], H, L);
            Wdh[j[u]] = H; Wdl[j[u]] = L;
        } else if (kind[u] == 3) {
            uint2 H; H.x = pack_h2(v[u].x, v[u].y); H.y = pack_h2(v[u].z, v[u].w);
            Woh[j[u]] = H;
        } else {
            uint2 H, L; split4(v[u], H, L);
            Wxh[j[u]] = H; Wxl[j[u]] = L;
        }
    }
}

// ---------------------------------------------------------------------------
// reduces
// ---------------------------------------------------------------------------
__global__ void reduce_dbl_kernel(const float* __restrict__ parts,
                                  float* __restrict__ dbl,
                                  __half* __restrict__ dbh,
                                  __half* __restrict__ dbll)
{
    int i = blockIdx.x * blockDim.x + threadIdx.x;
    if (i >= MROWS * NDP) return;
    float s = 0.f;
#pragma unroll
    for (int k = 0; k < 8; k++) s += parts[(size_t)k * MROWS * NDP + i];
    dbl[i] = s;
    int c = i & 127;
    if (c < 64) {
        int r = i >> 7;
        __half h = __float2half(s);
        dbh [r * DTR + c] = h;
        dbll[r * DTR + c] = __float2half(s - __half2float(h));
    }
}

__global__ void reduce_out_kernel(const float4* __restrict__ s0,
                                  const float4* __restrict__ s1,
                                  float4* __restrict__ out, int n4)
{
    int i = blockIdx.x * blockDim.x + threadIdx.x;
    if (i >= n4) return;
    float4 a = s0[i], b = s1[i];
    out[i] = make_float4(a.x + b.x, a.y + b.y, a.z + b.z, a.w + b.w);
}

// ---------------------------------------------------------------------------
// Tensor-core GEMM: 128x128 CTA, 256 threads (8 warps, 64x32 warp tile).
// TERMS = 1 (AhBh), 2 (+AlBh), 3 (+AhBl). BK=32, NS-stage cp.async.
// ---------------------------------------------------------------------------
#define AS_ST 40
#define BS_ST 136
#define A_PL  (128*AS_ST)
#define B_PL  (32*BS_ST)

__device__ __forceinline__ void cp16(uint32_t dst, const void* src) {
    asm volatile("cp.async.cg.shared.global [%0], [%1], 16;\n" :: "r"(dst), "l"(src));
}
__device__ __forceinline__ void ldsm4(uint32_t* r, uint32_t addr) {
    asm volatile("ldmatrix.sync.aligned.m8n8.x4.shared.b16 {%0,%1,%2,%3}, [%4];"
                 : "=r"(r[0]), "=r"(r[1]), "=r"(r[2]), "=r"(r[3]) : "r"(addr));
}
__device__ __forceinline__ void ldsm4t(uint32_t* r, uint32_t addr) {
    asm volatile("ldmatrix.sync.aligned.m8n8.x4.trans.shared.b16 {%0,%1,%2,%3}, [%4];"
                 : "=r"(r[0]), "=r"(r[1]), "=r"(r[2]), "=r"(r[3]) : "r"(addr));
}
__device__ __forceinline__ void mma_f16(float* c, const uint32_t* a, const uint32_t* b) {
    asm volatile("mma.sync.aligned.m16n8k16.row.col.f32.f16.f16.f32 "
                 "{%0,%1,%2,%3},{%4,%5,%6,%7},{%8,%9},{%0,%1,%2,%3};"
                 : "+f"(c[0]), "+f"(c[1]), "+f"(c[2]), "+f"(c[3])
                 : "r"(a[0]), "r"(a[1]), "r"(a[2]), "r"(a[3]), "r"(b[0]), "r"(b[1]));
}

template<int TERMS, int NS>
__global__ __launch_bounds__(256, 2)
void mma_gemm(const __half* __restrict__ Ah, const __half* __restrict__ Al,
              const __half* __restrict__ Bh, const __half* __restrict__ Bl,
              float* __restrict__ C, int Kchunk,
              int lda, int ldb, int ldc,
              size_t slabStride,
              const float* __restrict__ bias)
{
    constexpr int NA = (TERMS >= 2) ? 2 : 1;
    constexpr int NB = (TERMS >= 3) ? 2 : 1;
    constexpr int AH_OFF = 0;
    constexpr int AL_OFF = A_PL;
    constexpr int BH_OFF = NA * A_PL;
    constexpr int BL_OFF = NA * A_PL + B_PL;
    constexpr uint32_t STAGE_B = (NA * A_PL + NB * B_PL) * 2;

    extern __shared__ __align__(16) char dynsmem[];

    const int tid  = threadIdx.x;
    const int lane = tid & 31;
    const int wid  = tid >> 5;
    const int wm   = (wid >> 2) * 64;
    const int wn   = (wid & 3) * 32;
    const int bm   = blockIdx.y * 128;
    const int bn   = blockIdx.x * 128;
    const int kb   = blockIdx.z * Kchunk;

    C += (size_t)blockIdx.z * slabStride;

    const uint32_t sbase = (uint32_t)__cvta_generic_to_shared(dynsmem);

    float acc[4][4][4];
#pragma unroll
    for (int i = 0; i < 4; i++)
#pragma unroll
        for (int j = 0; j < 4; j++)
#pragma unroll
            for (int k = 0; k < 4; k++) acc[i][j][k] = 0.f;

    const int KT = Kchunk >> 5;

    const __half* Ahb = Ah + (size_t)bm * lda + kb;
    const __half* Alb = (TERMS >= 2) ? (Al + (size_t)bm * lda + kb) : nullptr;
    const __half* Bhb = Bh + (size_t)kb * ldb + bn;
    const __half* Blb = (TERMS >= 3) ? (Bl + (size_t)kb * ldb + bn) : nullptr;

#define ISSUE(stage, kt_) {                                                    \
        uint32_t sb = sbase + (uint32_t)(stage) * STAGE_B;                     \
        int k0 = (kt_) << 5;                                                   \
        _Pragma("unroll")                                                      \
        for (int rep = 0; rep < 2; rep++) {                                    \
            int idx = rep * 256 + tid;                                         \
            int arw = idx >> 2,  acc_ = (idx & 3) * 8;                         \
            int brw = idx >> 4,  bcc_ = (idx & 15) * 8;                        \
            cp16(sb + (AH_OFF + arw * AS_ST + acc_) * 2,                       \
                 Ahb + (size_t)arw * lda + k0 + acc_);                         \
            if (TERMS >= 2)                                                    \
                cp16(sb + (AL_OFF + arw * AS_ST + acc_) * 2,                   \
                     Alb + (size_t)arw * lda + k0 + acc_);                     \
            cp16(sb + (BH_OFF + brw * BS_ST + bcc_) * 2,                       \
                 Bhb + (size_t)(k0 + brw) * ldb + bcc_);                       \
            if (TERMS >= 3)                                                    \
                cp16(sb + (BL_OFF + brw * BS_ST + bcc_) * 2,                   \
                     Blb + (size_t)(k0 + brw) * ldb + bcc_);                   \
        }                                                                      \
        asm volatile("cp.async.commit_group;\n");                              \
    }

    ISSUE(0, 0);
    if (NS >= 3 && KT > 1) ISSUE(1, 1);

    const int arow = lane & 15;
    const int acol = (lane >> 4) * 8;

    for (int kt = 0; kt < KT; ++kt) {
        if (NS >= 3 && kt + 1 < KT) asm volatile("cp.async.wait_group 1;\n");
        else                        asm volatile("cp.async.wait_group 0;\n");
        __syncthreads();

        if (NS >= 3) { if (kt + 2 < KT) ISSUE((kt + 2) % NS, kt + 2); }
        else         { if (kt + 1 < KT) ISSUE((kt + 1) & 1,  kt + 1); }

        uint32_t sb = sbase + (uint32_t)(kt % NS) * STAGE_B;

#pragma unroll
        for (int ks = 0; ks < 2; ks++) {
            const int kso = ks * 16;
            uint32_t ah[4][4], bx[4][2];
#pragma unroll
            for (int i = 0; i < 4; i++)
                ldsm4(ah[i], sb + (uint32_t)(AH_OFF + (wm + i * 16 + arow) * AS_ST + kso + acol) * 2);
#pragma unroll
            for (int jj = 0; jj < 2; jj++) {
                uint32_t r[4];
                ldsm4t(r, sb + (uint32_t)(BH_OFF + (kso + arow) * BS_ST + wn + jj * 16 + acol) * 2);
                bx[2 * jj][0] = r[0]; bx[2 * jj][1] = r[1];
                bx[2 * jj + 1][0] = r[2]; bx[2 * jj + 1][1] = r[3];
            }
#pragma unroll
            for (int i = 0; i < 4; i++)
#pragma unroll
                for (int j = 0; j < 4; j++) mma_f16(acc[i][j], ah[i], bx[j]);

            if (TERMS >= 2) {
                uint32_t al[4][4];
#pragma unroll
                for (int i = 0; i < 4; i++)
                    ldsm4(al[i], sb + (uint32_t)(AL_OFF + (wm + i * 16 + arow) * AS_ST + kso + acol) * 2);
#pragma unroll
                for (int i = 0; i < 4; i++)
#pragma unroll
                    for (int j = 0; j < 4; j++) mma_f16(acc[i][j], al[i], bx[j]);
            }
            if (TERMS >= 3) {
#pragma unroll
                for (int jj = 0; jj < 2; jj++) {
                    uint32_t r[4];
                    ldsm4t(r, sb + (uint32_t)(BL_OFF + (kso + arow) * BS_ST + wn + jj * 16 + acol) * 2);
                    bx[2 * jj][0] = r[0]; bx[2 * jj][1] = r[1];
                    bx[2 * jj + 1][0] = r[2]; bx[2 * jj + 1][1] = r[3];
                }
#pragma unroll
                for (int i = 0; i < 4; i++)
#pragma unroll
                    for (int j = 0; j < 4; j++) mma_f16(acc[i][j], ah[i], bx[j]);
            }
        }
    }
#undef ISSUE

    const bool sp = (bias != nullptr);
#pragma unroll
    for (int i = 0; i < 4; i++) {
        int row0 = bm + wm + i * 16 + (lane >> 2);
#pragma unroll
        for (int j = 0; j < 4; j++) {
            int col = bn + wn + j * 8 + (lane & 3) * 2;
            float v0 = acc[i][j][0], v1 = acc[i][j][1];
            float v2 = acc[i][j][2], v3 = acc[i][j][3];
            if (sp) {
                float b0 = bias[col], b1 = bias[col + 1];
                v0 += b0; v1 += b1; v2 += b0; v3 += b1;
                v0 = (v0 > 20.f) ? v0 : log1pf(__expf(v0));
                v1 = (v1 > 20.f) ? v1 : log1pf(__expf(v1));
                v2 = (v2 > 20.f) ? v2 : log1pf(__expf(v2));
                v3 = (v3 > 20.f) ? v3 : log1pf(__expf(v3));
            }
            *(float2*)(C + (size_t)row0 * ldc + col)       = make_float2(v0, v1);
            *(float2*)(C + (size_t)(row0 + 8) * ldc + col) = make_float2(v2, v3);
        }
    }
}

// ---------------------------------------------------------------------------
// Depthwise causal conv (width 4) + bias + SiLU — SLIDING WINDOW over 4
// consecutive l per thread (7 tap loads instead of 16; bitwise-identical
// per-element accumulation order). Only change this round.
// ---------------------------------------------------------------------------
__global__ void conv_silu_kernel(const float* __restrict__ xz,
                                 const float* __restrict__ conv_w,
                                 const float* __restrict__ conv_b,
                                 float* __restrict__ xc,
                                 __half* __restrict__ xch,
                                 __half* __restrict__ xcl)
{
    int t = blockIdx.x * blockDim.x + threadIdx.x;
    if (t >= MROWS * DI / 4) return;
    const int d  = t & (DI - 1);
    const int lg = (t >> 11) & (LC / 4 - 1);     // l-group 0..255
    const int b  = t >> 19;
    const int l0 = lg * 4;

    // window loads: rows l0-3 .. l0+3 at column d (7 loads, independent)
    float win[7];
    const float* base = xz + (size_t)(b * LC) * NXZ + d;
#pragma unroll
    for (int k = 0; k < 7; k++) {
        int ll = l0 - 3 + k;
        win[k] = (ll >= 0) ? __ldg(base + (size_t)ll * NXZ) : 0.f;
    }

    float w[DCNV];
#pragma unroll
    for (int j = 0; j < DCNV; j++) w[j] = conv_w[d * DCNV + j];
    const float bv = conv_b[d];

    const size_t o = (size_t)(b * LC + l0) * DI + d;
#pragma unroll
    for (int u = 0; u < 4; u++) {
        // output l = l0+u uses taps win[u .. u+3] (same order as scalar version)
        float acc = bv;
#pragma unroll
        for (int j = 0; j < DCNV; j++)
            acc += win[u + j] * w[j];
        float v = acc / (1.f + __expf(-acc));

        xc[o + (size_t)u * DI] = v;
        __half h = __float2half(v);
        xch[o + (size_t)u * DI] = h;
        xcl[o + (size_t)u * DI] = __float2half(v - __half2float(h));
    }
}

// ---------------------------------------------------------------------------
// Selective scan: 8 lanes/channel, 2 states/lane, chunk-4 double buffering.
// 128-thread blocks (round-14 measured-best).
// ---------------------------------------------------------------------------
#define SCH 4
__global__ __launch_bounds__(128)
void scan_kernel(const float* __restrict__ dt,
                 const float* __restrict__ xc,
                 const float* __restrict__ dbl,
                 const float* __restrict__ xz,
                 const float* __restrict__ A_log,
                 const float* __restrict__ D_par,
                 __half* __restrict__ yh)
{
    const int gtid = blockIdx.x * 128 + threadIdx.x;
    const int ch = gtid >> 3;
    const int nl = gtid & 7;
    const int n0 = nl * 2;
    const int b  = ch >> 11;
    const int d  = ch & (DI - 1);

    const float An0 = -expf(A_log[d * DS + n0]);
    const float An1 = -expf(A_log[d * DS + n0 + 1]);
    const float Dv  = D_par[d];
    float h0 = 0.f, h1 = 0.f;

    const size_t rowbase = (size_t)b * LC;
    const float* pdt = dt  + rowbase * DI + d;
    const float* pxc = xc  + rowbase * DI + d;
    const float* pBC = dbl + rowbase * NDP + 64 + n0;
    const float* pz  = xz  + rowbase * NXZ + DI + d;
    __half* pyh = yh + rowbase * DI + d;

    float  dtb_[2][SCH], xcb[2][SCH], zb[2][SCH];
    float2 Bb[2][SCH], Cb[2][SCH];

#define LOADG(g_, p_) {                                                        \
        _Pragma("unroll")                                                      \
        for (int u = 0; u < SCH; u++) {                                        \
            size_t row = (size_t)((g_) * SCH + u);                             \
            dtb_[p_][u] = __ldg(pdt + row * DI);                               \
            xcb[p_][u]  = __ldg(pxc + row * DI);                               \
            Bb[p_][u]   = __ldg((const float2*)(pBC + row * NDP));             \
            Cb[p_][u]   = __ldg((const float2*)(pBC + row * NDP + DS));        \
            zb[p_][u]   = (nl == 0) ? __ldg(pz + row * NXZ) : 0.f;             \
        }                                                                      \
    }

    const int NG = LC / SCH;
    LOADG(0, 0);

#pragma unroll 2
    for (int g = 0; g < NG; g++) {
        const int p = g & 1;
        if (g + 1 < NG) LOADG(g + 1, p ^ 1);

#pragma unroll
        for (int u = 0; u < SCH; u++) {
            float dtv = dtb_[p][u], xcv = xcb[p][u];
            float2 Bv = Bb[p][u],   Cv  = Cb[p][u];

            float dx = dtv * xcv;
            h0 = __expf(dtv * An0) * h0 + dx * Bv.x;
            h1 = __expf(dtv * An1) * h1 + dx * Bv.y;

            float yv = h0 * Cv.x + h1 * Cv.y;
            yv += __shfl_xor_sync(0xffffffffu, yv, 4);
            yv += __shfl_xor_sync(0xffffffffu, yv, 2);
            yv += __shfl_xor_sync(0xffffffffu, yv, 1);

            if (nl == 0) {
                float zv  = zb[p][u];
                float sil = zv / (1.f + __expf(-zv));
                float yo  = (yv + xcv * Dv) * sil;
                pyh[(size_t)(g * SCH + u) * DI] = __float2half(yo);
            }
        }
    }
#undef LOADG
}

// ---------------------------------------------------------------------------
extern "C" void kernel_launch(void* const* d_in, const int* in_sizes, int n_in,
                              void* d_out, int out_size)
{
    const float* x      = (const float*)d_in[0];
    const float* W_in   = (const float*)d_in[1];
    const float* conv_w = (const float*)d_in[2];
    const float* conv_b = (const float*)d_in[3];
    const float* W_x    = (const float*)d_in[4];
    const float* W_dt   = (const float*)d_in[5];
    const float* b_dt   = (const float*)d_in[6];
    const float* A_log  = (const float*)d_in[7];
    const float* D_par  = (const float*)d_in[8];
    const float* W_out  = (const float*)d_in[9];
    float* out = (float*)d_out;

    float *xz, *xc, *dtb, *dbl, *dblp, *osp;
    __half *xh, *Wih, *Wxh, *Wxl, *xch, *xcl,
           *dbh, *dbll, *Wdh, *Wdl, *yh, *Woh;
    cudaGetSymbolAddress((void**)&xz,   g_xz);
    cudaGetSymbolAddress((void**)&xc,   g_xc);
    cudaGetSymbolAddress((void**)&dtb,  g_dt);
    cudaGetSymbolAddress((void**)&dbl,  g_dbl);
    cudaGetSymbolAddress((void**)&dblp, g_dblp);
    cudaGetSymbolAddress((void**)&osp,  g_osp);
    cudaGetSymbolAddress((void**)&xh,   g_xh);
    cudaGetSymbolAddress((void**)&Wih,  g_Wih);
    cudaGetSymbolAddress((void**)&Wxh,  g_Wxh);  cudaGetSymbolAddress((void**)&Wxl,  g_Wxl);
    cudaGetSymbolAddress((void**)&xch,  g_xch);  cudaGetSymbolAddress((void**)&xcl,  g_xcl);
    cudaGetSymbolAddress((void**)&dbh,  g_dbh);  cudaGetSymbolAddress((void**)&dbll, g_dbll);
    cudaGetSymbolAddress((void**)&Wdh,  g_Wdh);  cudaGetSymbolAddress((void**)&Wdl,  g_Wdl);
    cudaGetSymbolAddress((void**)&yh,   g_yh);
    cudaGetSymbolAddress((void**)&Woh,  g_Woh);

    const int SMEM1 = 3 * (1 * A_PL + 1 * B_PL) * 2;
    const int SMEM3 = 2 * (2 * A_PL + 2 * B_PL) * 2;
    cudaFuncSetAttribute((const void*)mma_gemm<1, 3>,
                         cudaFuncAttributeMaxDynamicSharedMemorySize, SMEM1);
    cudaFuncSetAttribute((const void*)mma_gemm<3, 2>,
                         cudaFuncAttributeMaxDynamicSharedMemorySize, SMEM3);

    // 0) all input conversions (ILP x4)
    prep_kernel<<<(SEG5 + 1023) / 1024, 256>>>(
        (const float4*)x, (const float4*)W_in, (const float4*)W_dt,
        (const float4*)W_out, W_x,
        (uint2*)xh, (uint2*)Wih,
        (uint2*)Wdh, (uint2*)Wdl, (uint2*)Woh, (uint2*)Wxh, (uint2*)Wxl);

    // 1) xz = x @ W_in (1-term)
    mma_gemm<1, 3><<<dim3(NXZ / 128, MROWS / 128, 1), 256, SMEM1>>>(
        xh, nullptr, Wih, nullptr, xz, DM, DM, NXZ, NXZ, 0, nullptr);

    // 2) conv + SiLU (+ fp16 split), sliding-window x4 in l
    conv_silu_kernel<<<(MROWS * DI / 4 + 255) / 256, 256>>>(
        xz, conv_w, conv_b, xc, xch, xcl);

    // 3) dbl = xc @ W_x_padded (3-term), K-split 8
    mma_gemm<3, 2><<<dim3(1, MROWS / 128, 8), 256, SMEM3>>>(
        xch, xcl, Wxh, Wxl, dblp, DI / 8, DI, NDP, NDP,
        (size_t)MROWS * NDP, nullptr);

    // 4) reduce partials + compact fp16 of dt-rank slice
    reduce_dbl_kernel<<<(MROWS * NDP + 255) / 256, 256>>>(dblp, dbl, dbh, dbll);

    // 5) dt = softplus(dbl[:,:64] @ W_dt + b_dt) (3-term)
    mma_gemm<3, 2><<<dim3(DI / 128, MROWS / 128, 1), 256, SMEM3>>>(
        dbh, dbll, Wdh, Wdl, dtb, DTR, DTR, DI, DI, 0, b_dt);

    // 6) selective scan -> y (fp16 hi), 128-thread blocks
    scan_kernel<<<(BC * DI * 8) / 128, 128>>>(dtb, xc, dbl, xz, A_log, D_par, yh);

    // 7) out = y @ W_out (1-term), K-split 2 -> slabs
    mma_gemm<1, 3><<<dim3(DM / 128, MROWS / 128, 2), 256, SMEM1>>>(
        yh, nullptr, Woh, nullptr, osp, DI / 2, DI, DM, DM,
        (size_t)MROWS * DM, nullptr);

    // 8) out = slab0 + slab1
    reduce_out_kernel<<<(MROWS * DM / 4 + 255) / 256, 256>>>(
        (const float4*)osp, (const float4*)(osp + (size_t)MROWS * DM),
        (float4*)out, MROWS * DM / 4);
}

// round 16
// speedup vs baseline: 1.1166x; 1.0230x over previous
#include <cuda_runtime.h>
#include <cuda_fp16.h>
#include <cstdint>

// Problem dims (fixed)
#define BC   2
#define LC   1024
#define DM   1024
#define DI   2048
#define DS   16
#define DCNV 4
#define DTR  64
#define MROWS (BC*LC)      // 2048
#define NXZ   (2*DI)       // 4096
#define NDP   128

// ---------------- scratch (device globals) ----------------
__device__ float g_xz  [MROWS * NXZ];
__device__ float g_xc  [MROWS * DI];
__device__ float g_dt  [MROWS * DI];
__device__ float g_dbl [MROWS * NDP];
__device__ float g_dblp[8 * MROWS * NDP];
__device__ float g_osp [2 * MROWS * DM];

__device__ __half g_xh  [MROWS * DM];
__device__ __half g_Wih [DM * NXZ];
__device__ __half g_Wxh [DI * NDP],    g_Wxl [DI * NDP];
__device__ __half g_xch [MROWS * DI],  g_xcl [MROWS * DI];
__device__ __half g_dbh [MROWS * DTR], g_dbll[MROWS * DTR];
__device__ __half g_Wdh [DTR * DI],    g_Wdl [DTR * DI];
__device__ __half g_yh  [MROWS * DI];
__device__ __half g_Woh [DI * DM];

// ---------------------------------------------------------------------------
// helpers
// ---------------------------------------------------------------------------
__device__ __forceinline__ uint32_t pack_h2(float a, float b) {
    __half2 h = __floats2half2_rn(a, b);
    return *reinterpret_cast<uint32_t*>(&h);
}
__device__ __forceinline__ void split4(float4 v, uint2& H, uint2& L) {
    float hx = __half2float(__float2half(v.x));
    float hy = __half2float(__float2half(v.y));
    float hz = __half2float(__float2half(v.z));
    float hw = __half2float(__float2half(v.w));
    H.x = pack_h2(v.x, v.y);            H.y = pack_h2(v.z, v.w);
    L.x = pack_h2(v.x - hx, v.y - hy);  L.y = pack_h2(v.z - hz, v.w - hw);
}

// ---------------------------------------------------------------------------
// Fused conversion, ILP x4 (round-14 measured-best). Segments (float4 units):
//   [0,SEG1): x -> xh (hi)             [SEG1,SEG2): W_in -> Wih (hi)
//   [SEG2,SEG3): W_dt -> hi/lo         [SEG3,SEG4): W_out -> Woh (hi)
//   [SEG4,SEG5): W_x -> hi/lo padded [DI x 128]
// ---------------------------------------------------------------------------
#define SEG1  524288
#define SEG2 1572864
#define SEG3 1605632
#define SEG4 2129920
#define SEG5 2195456

__device__ __forceinline__ const float4* seg_src(
    int i, const float4* x, const float4* W_in, const float4* W_dt,
    const float4* W_out, const float* W_x, int& kind, int& j)
{
    if (i < SEG1)      { kind = 0; j = i;        return x + j; }
    else if (i < SEG2) { kind = 1; j = i - SEG1; return W_in + j; }
    else if (i < SEG3) { kind = 2; j = i - SEG2; return W_dt + j; }
    else if (i < SEG4) { kind = 3; j = i - SEG3; return W_out + j; }
    kind = 4; j = i - SEG4;
    int idx = j * 4;
    int r = idx >> 7, c = idx & 127;
    return (c < 96) ? (const float4*)(W_x + (size_t)r * 96 + c) : nullptr;
}

__global__ void prep_kernel(const float4* __restrict__ x,
                            const float4* __restrict__ W_in,
                            const float4* __restrict__ W_dt,
                            const float4* __restrict__ W_out,
                            const float*  __restrict__ W_x,
                            uint2* __restrict__ xh,
                            uint2* __restrict__ Wih,
                            uint2* __restrict__ Wdh, uint2* __restrict__ Wdl,
                            uint2* __restrict__ Woh,
                            uint2* __restrict__ Wxh, uint2* __restrict__ Wxl)
{
    int base = (blockIdx.x * blockDim.x) * 4 + threadIdx.x;
    float4 v[4];
    int kind[4], j[4];
    bool ok[4];
#pragma unroll
    for (int u = 0; u < 4; u++) {
        int i = base + u * blockDim.x;
        ok[u] = (i < SEG5);
        if (ok[u]) {
            const float4* p = seg_src(i, x, W_in, W_dt, W_out, W_x, kind[u], j[u]);
            v[u] = p ? __ldg(p) : make_float4(0.f, 0.f, 0.f, 0.f);
        }
    }
#pragma unroll
    for (int u = 0; u < 4; u++) {
        if (!ok[u]) continue;
        if (kind[u] == 0) {
            uint2 H; H.x = pack_h2(v[u].x, v[u].y); H.y = pack_h2(v[u].z, v[u].w);
            xh[j[u]] = H;
        } else if (kind[u] == 1) {
            uint2 H; H.x = pack_h2(v[u].x, v[u].y); H.y = pack_h2(v[u].z, v[u].w);
            Wih[j[u]] = H;
        } else if (kind[u] == 2) {
            uint2 H, L; split4(v[u], H, L);
            Wdh[j[u]] = H; Wdl[j[u]] = L;
        } else if (kind[u] == 3) {
            uint2 H; H.x = pack_h2(v[u].x, v[u].y); H.y = pack_h2(v[u].z, v[u].w);
            Woh[j[u]] = H;
        } else {
            uint2 H, L; split4(v[u], H, L);
            Wxh[j[u]] = H; Wxl[j[u]] = L;
        }
    }
}

// ---------------------------------------------------------------------------
// reduces
// ---------------------------------------------------------------------------
__global__ void reduce_dbl_kernel(const float* __restrict__ parts,
                                  float* __restrict__ dbl,
                                  __half* __restrict__ dbh,
                                  __half* __restrict__ dbll)
{
    int i = blockIdx.x * blockDim.x + threadIdx.x;
    if (i >= MROWS * NDP) return;
    float s = 0.f;
#pragma unroll
    for (int k = 0; k < 8; k++) s += parts[(size_t)k * MROWS * NDP + i];
    dbl[i] = s;
    int c = i & 127;
    if (c < 64) {
        int r = i >> 7;
        __half h = __float2half(s);
        dbh [r * DTR + c] = h;
        dbll[r * DTR + c] = __float2half(s - __half2float(h));
    }
}

__global__ void reduce_out_kernel(const float4* __restrict__ s0,
                                  const float4* __restrict__ s1,
                                  float4* __restrict__ out, int n4)
{
    int i = blockIdx.x * blockDim.x + threadIdx.x;
    if (i >= n4) return;
    float4 a = s0[i], b = s1[i];
    out[i] = make_float4(a.x + b.x, a.y + b.y, a.z + b.z, a.w + b.w);
}

// ---------------------------------------------------------------------------
// Tensor-core GEMM: 128x128 CTA, 256 threads (8 warps, 64x32 warp tile).
// TERMS = 1 (AhBh), 2 (+AlBh), 3 (+AhBl). BK=32, NS-stage cp.async.
// ---------------------------------------------------------------------------
#define AS_ST 40
#define BS_ST 136
#define A_PL  (128*AS_ST)
#define B_PL  (32*BS_ST)

__device__ __forceinline__ void cp16(uint32_t dst, const void* src) {
    asm volatile("cp.async.cg.shared.global [%0], [%1], 16;\n" :: "r"(dst), "l"(src));
}
__device__ __forceinline__ void ldsm4(uint32_t* r, uint32_t addr) {
    asm volatile("ldmatrix.sync.aligned.m8n8.x4.shared.b16 {%0,%1,%2,%3}, [%4];"
                 : "=r"(r[0]), "=r"(r[1]), "=r"(r[2]), "=r"(r[3]) : "r"(addr));
}
__device__ __forceinline__ void ldsm4t(uint32_t* r, uint32_t addr) {
    asm volatile("ldmatrix.sync.aligned.m8n8.x4.trans.shared.b16 {%0,%1,%2,%3}, [%4];"
                 : "=r"(r[0]), "=r"(r[1]), "=r"(r[2]), "=r"(r[3]) : "r"(addr));
}
__device__ __forceinline__ void mma_f16(float* c, const uint32_t* a, const uint32_t* b) {
    asm volatile("mma.sync.aligned.m16n8k16.row.col.f32.f16.f16.f32 "
                 "{%0,%1,%2,%3},{%4,%5,%6,%7},{%8,%9},{%0,%1,%2,%3};"
                 : "+f"(c[0]), "+f"(c[1]), "+f"(c[2]), "+f"(c[3])
                 : "r"(a[0]), "r"(a[1]), "r"(a[2]), "r"(a[3]), "r"(b[0]), "r"(b[1]));
}

template<int TERMS, int NS>
__global__ __launch_bounds__(256, 2)
void mma_gemm(const __half* __restrict__ Ah, const __half* __restrict__ Al,
              const __half* __restrict__ Bh, const __half* __restrict__ Bl,
              float* __restrict__ C, int Kchunk,
              int lda, int ldb, int ldc,
              size_t slabStride,
              const float* __restrict__ bias)
{
    constexpr int NA = (TERMS >= 2) ? 2 : 1;
    constexpr int NB = (TERMS >= 3) ? 2 : 1;
    constexpr int AH_OFF = 0;
    constexpr int AL_OFF = A_PL;
    constexpr int BH_OFF = NA * A_PL;
    constexpr int BL_OFF = NA * A_PL + B_PL;
    constexpr uint32_t STAGE_B = (NA * A_PL + NB * B_PL) * 2;

    extern __shared__ __align__(16) char dynsmem[];

    const int tid  = threadIdx.x;
    const int lane = tid & 31;
    const int wid  = tid >> 5;
    const int wm   = (wid >> 2) * 64;
    const int wn   = (wid & 3) * 32;
    const int bm   = blockIdx.y * 128;
    const int bn   = blockIdx.x * 128;
    const int kb   = blockIdx.z * Kchunk;

    C += (size_t)blockIdx.z * slabStride;

    const uint32_t sbase = (uint32_t)__cvta_generic_to_shared(dynsmem);

    float acc[4][4][4];
#pragma unroll
    for (int i = 0; i < 4; i++)
#pragma unroll
        for (int j = 0; j < 4; j++)
#pragma unroll
            for (int k = 0; k < 4; k++) acc[i][j][k] = 0.f;

    const int KT = Kchunk >> 5;

    const __half* Ahb = Ah + (size_t)bm * lda + kb;
    const __half* Alb = (TERMS >= 2) ? (Al + (size_t)bm * lda + kb) : nullptr;
    const __half* Bhb = Bh + (size_t)kb * ldb + bn;
    const __half* Blb = (TERMS >= 3) ? (Bl + (size_t)kb * ldb + bn) : nullptr;

#define ISSUE(stage, kt_) {                                                    \
        uint32_t sb = sbase + (uint32_t)(stage) * STAGE_B;                     \
        int k0 = (kt_) << 5;                                                   \
        _Pragma("unroll")                                                      \
        for (int rep = 0; rep < 2; rep++) {                                    \
            int idx = rep * 256 + tid;                                         \
            int arw = idx >> 2,  acc_ = (idx & 3) * 8;                         \
            int brw = idx >> 4,  bcc_ = (idx & 15) * 8;                        \
            cp16(sb + (AH_OFF + arw * AS_ST + acc_) * 2,                       \
                 Ahb + (size_t)arw * lda + k0 + acc_);                         \
            if (TERMS >= 2)                                                    \
                cp16(sb + (AL_OFF + arw * AS_ST + acc_) * 2,                   \
                     Alb + (size_t)arw * lda + k0 + acc_);                     \
            cp16(sb + (BH_OFF + brw * BS_ST + bcc_) * 2,                       \
                 Bhb + (size_t)(k0 + brw) * ldb + bcc_);                       \
            if (TERMS >= 3)                                                    \
                cp16(sb + (BL_OFF + brw * BS_ST + bcc_) * 2,                   \
                     Blb + (size_t)(k0 + brw) * ldb + bcc_);                   \
        }                                                                      \
        asm volatile("cp.async.commit_group;\n");                              \
    }

    ISSUE(0, 0);
    if (NS >= 3 && KT > 1) ISSUE(1, 1);

    const int arow = lane & 15;
    const int acol = (lane >> 4) * 8;

    for (int kt = 0; kt < KT; ++kt) {
        if (NS >= 3 && kt + 1 < KT) asm volatile("cp.async.wait_group 1;\n");
        else                        asm volatile("cp.async.wait_group 0;\n");
        __syncthreads();

        if (NS >= 3) { if (kt + 2 < KT) ISSUE((kt + 2) % NS, kt + 2); }
        else         { if (kt + 1 < KT) ISSUE((kt + 1) & 1,  kt + 1); }

        uint32_t sb = sbase + (uint32_t)(kt % NS) * STAGE_B;

#pragma unroll
        for (int ks = 0; ks < 2; ks++) {
            const int kso = ks * 16;
            uint32_t ah[4][4], bx[4][2];
#pragma unroll
            for (int i = 0; i < 4; i++)
                ldsm4(ah[i], sb + (uint32_t)(AH_OFF + (wm + i * 16 + arow) * AS_ST + kso + acol) * 2);
#pragma unroll
            for (int jj = 0; jj < 2; jj++) {
                uint32_t r[4];
                ldsm4t(r, sb + (uint32_t)(BH_OFF + (kso + arow) * BS_ST + wn + jj * 16 + acol) * 2);
                bx[2 * jj][0] = r[0]; bx[2 * jj][1] = r[1];
                bx[2 * jj + 1][0] = r[2]; bx[2 * jj + 1][1] = r[3];
            }
#pragma unroll
            for (int i = 0; i < 4; i++)
#pragma unroll
                for (int j = 0; j < 4; j++) mma_f16(acc[i][j], ah[i], bx[j]);

            if (TERMS >= 2) {
                uint32_t al[4][4];
#pragma unroll
                for (int i = 0; i < 4; i++)
                    ldsm4(al[i], sb + (uint32_t)(AL_OFF + (wm + i * 16 + arow) * AS_ST + kso + acol) * 2);
#pragma unroll
                for (int i = 0; i < 4; i++)
#pragma unroll
                    for (int j = 0; j < 4; j++) mma_f16(acc[i][j], al[i], bx[j]);
            }
            if (TERMS >= 3) {
#pragma unroll
                for (int jj = 0; jj < 2; jj++) {
                    uint32_t r[4];
                    ldsm4t(r, sb + (uint32_t)(BL_OFF + (kso + arow) * BS_ST + wn + jj * 16 + acol) * 2);
                    bx[2 * jj][0] = r[0]; bx[2 * jj][1] = r[1];
                    bx[2 * jj + 1][0] = r[2]; bx[2 * jj + 1][1] = r[3];
                }
#pragma unroll
                for (int i = 0; i < 4; i++)
#pragma unroll
                    for (int j = 0; j < 4; j++) mma_f16(acc[i][j], ah[i], bx[j]);
            }
        }
    }
#undef ISSUE

    const bool sp = (bias != nullptr);
#pragma unroll
    for (int i = 0; i < 4; i++) {
        int row0 = bm + wm + i * 16 + (lane >> 2);
#pragma unroll
        for (int j = 0; j < 4; j++) {
            int col = bn + wn + j * 8 + (lane & 3) * 2;
            float v0 = acc[i][j][0], v1 = acc[i][j][1];
            float v2 = acc[i][j][2], v3 = acc[i][j][3];
            if (sp) {
                float b0 = bias[col], b1 = bias[col + 1];
                v0 += b0; v1 += b1; v2 += b0; v3 += b1;
                v0 = (v0 > 20.f) ? v0 : log1pf(__expf(v0));
                v1 = (v1 > 20.f) ? v1 : log1pf(__expf(v1));
                v2 = (v2 > 20.f) ? v2 : log1pf(__expf(v2));
                v3 = (v3 > 20.f) ? v3 : log1pf(__expf(v3));
            }
            *(float2*)(C + (size_t)row0 * ldc + col)       = make_float2(v0, v1);
            *(float2*)(C + (size_t)(row0 + 8) * ldc + col) = make_float2(v2, v3);
        }
    }
}

// ---------------------------------------------------------------------------
// Depthwise causal conv (width 4) + bias + SiLU — sliding-window x4 in l
// (round-15 measured-best).
// ---------------------------------------------------------------------------
__global__ void conv_silu_kernel(const float* __restrict__ xz,
                                 const float* __restrict__ conv_w,
                                 const float* __restrict__ conv_b,
                                 float* __restrict__ xc,
                                 __half* __restrict__ xch,
                                 __half* __restrict__ xcl)
{
    int t = blockIdx.x * blockDim.x + threadIdx.x;
    if (t >= MROWS * DI / 4) return;
    const int d  = t & (DI - 1);
    const int lg = (t >> 11) & (LC / 4 - 1);
    const int b  = t >> 19;
    const int l0 = lg * 4;

    float win[7];
    const float* base = xz + (size_t)(b * LC) * NXZ + d;
#pragma unroll
    for (int k = 0; k < 7; k++) {
        int ll = l0 - 3 + k;
        win[k] = (ll >= 0) ? __ldg(base + (size_t)ll * NXZ) : 0.f;
    }

    float w[DCNV];
#pragma unroll
    for (int j = 0; j < DCNV; j++) w[j] = conv_w[d * DCNV + j];
    const float bv = conv_b[d];

    const size_t o = (size_t)(b * LC + l0) * DI + d;
#pragma unroll
    for (int u = 0; u < 4; u++) {
        float acc = bv;
#pragma unroll
        for (int j = 0; j < DCNV; j++)
            acc += win[u + j] * w[j];
        float v = acc / (1.f + __expf(-acc));

        xc[o + (size_t)u * DI] = v;
        __half h = __float2half(v);
        xch[o + (size_t)u * DI] = h;
        xcl[o + (size_t)u * DI] = __float2half(v - __half2float(h));
    }
}

// ---------------------------------------------------------------------------
// Selective scan v3: 4 lanes/channel, 4 states/lane, float4 B/C loads,
// 2-step shfl reduce, chunk-4 double buffering. 64-thread blocks -> 256 CTAs.
// ---------------------------------------------------------------------------
#define SCH 4
__global__ __launch_bounds__(64)
void scan_kernel(const float* __restrict__ dt,
                 const float* __restrict__ xc,
                 const float* __restrict__ dbl,
                 const float* __restrict__ xz,
                 const float* __restrict__ A_log,
                 const float* __restrict__ D_par,
                 __half* __restrict__ yh)
{
    const int gtid = blockIdx.x * 64 + threadIdx.x;
    const int ch = gtid >> 2;          // 0..4095
    const int nl = gtid & 3;           // lane-in-channel
    const int n0 = nl * 4;
    const int b  = ch >> 11;
    const int d  = ch & (DI - 1);

    float An[4];
#pragma unroll
    for (int q = 0; q < 4; q++) An[q] = -expf(A_log[d * DS + n0 + q]);
    const float Dv = D_par[d];
    float h[4] = {0.f, 0.f, 0.f, 0.f};

    const size_t rowbase = (size_t)b * LC;
    const float* pdt = dt  + rowbase * DI + d;
    const float* pxc = xc  + rowbase * DI + d;
    const float* pBC = dbl + rowbase * NDP + 64 + n0;
    const float* pz  = xz  + rowbase * NXZ + DI + d;
    __half* pyh = yh + rowbase * DI + d;

    float  dtb_[2][SCH], xcb[2][SCH], zb[2][SCH];
    float4 Bb[2][SCH], Cb[2][SCH];

#define LOADG(g_, p_) {                                                        \
        _Pragma("unroll")                                                      \
        for (int u = 0; u < SCH; u++) {                                        \
            size_t row = (size_t)((g_) * SCH + u);                             \
            dtb_[p_][u] = __ldg(pdt + row * DI);                               \
            xcb[p_][u]  = __ldg(pxc + row * DI);                               \
            Bb[p_][u]   = __ldg((const float4*)(pBC + row * NDP));             \
            Cb[p_][u]   = __ldg((const float4*)(pBC + row * NDP + DS));        \
            zb[p_][u]   = (nl == 0) ? __ldg(pz + row * NXZ) : 0.f;             \
        }                                                                      \
    }

    const int NG = LC / SCH;
    LOADG(0, 0);

#pragma unroll 2
    for (int g = 0; g < NG; g++) {
        const int p = g & 1;
        if (g + 1 < NG) LOADG(g + 1, p ^ 1);

#pragma unroll
        for (int u = 0; u < SCH; u++) {
            float dtv = dtb_[p][u], xcv = xcb[p][u];
            float4 Bv = Bb[p][u],   Cv  = Cb[p][u];

            float dx = dtv * xcv;
            h[0] = __expf(dtv * An[0]) * h[0] + dx * Bv.x;
            h[1] = __expf(dtv * An[1]) * h[1] + dx * Bv.y;
            h[2] = __expf(dtv * An[2]) * h[2] + dx * Bv.z;
            h[3] = __expf(dtv * An[3]) * h[3] + dx * Bv.w;

            float yv = h[0] * Cv.x + h[1] * Cv.y + h[2] * Cv.z + h[3] * Cv.w;
            yv += __shfl_xor_sync(0xffffffffu, yv, 2);
            yv += __shfl_xor_sync(0xffffffffu, yv, 1);

            if (nl == 0) {
                float zv  = zb[p][u];
                float sil = zv / (1.f + __expf(-zv));
                float yo  = (yv + xcv * Dv) * sil;
                pyh[(size_t)(g * SCH + u) * DI] = __float2half(yo);
            }
        }
    }
#undef LOADG
}

// ---------------------------------------------------------------------------
extern "C" void kernel_launch(void* const* d_in, const int* in_sizes, int n_in,
                              void* d_out, int out_size)
{
    const float* x      = (const float*)d_in[0];
    const float* W_in   = (const float*)d_in[1];
    const float* conv_w = (const float*)d_in[2];
    const float* conv_b = (const float*)d_in[3];
    const float* W_x    = (const float*)d_in[4];
    const float* W_dt   = (const float*)d_in[5];
    const float* b_dt   = (const float*)d_in[6];
    const float* A_log  = (const float*)d_in[7];
    const float* D_par  = (const float*)d_in[8];
    const float* W_out  = (const float*)d_in[9];
    float* out = (float*)d_out;

    float *xz, *xc, *dtb, *dbl, *dblp, *osp;
    __half *xh, *Wih, *Wxh, *Wxl, *xch, *xcl,
           *dbh, *dbll, *Wdh, *Wdl, *yh, *Woh;
    cudaGetSymbolAddress((void**)&xz,   g_xz);
    cudaGetSymbolAddress((void**)&xc,   g_xc);
    cudaGetSymbolAddress((void**)&dtb,  g_dt);
    cudaGetSymbolAddress((void**)&dbl,  g_dbl);
    cudaGetSymbolAddress((void**)&dblp, g_dblp);
    cudaGetSymbolAddress((void**)&osp,  g_osp);
    cudaGetSymbolAddress((void**)&xh,   g_xh);
    cudaGetSymbolAddress((void**)&Wih,  g_Wih);
    cudaGetSymbolAddress((void**)&Wxh,  g_Wxh);  cudaGetSymbolAddress((void**)&Wxl,  g_Wxl);
    cudaGetSymbolAddress((void**)&xch,  g_xch);  cudaGetSymbolAddress((void**)&xcl,  g_xcl);
    cudaGetSymbolAddress((void**)&dbh,  g_dbh);  cudaGetSymbolAddress((void**)&dbll, g_dbll);
    cudaGetSymbolAddress((void**)&Wdh,  g_Wdh);  cudaGetSymbolAddress((void**)&Wdl,  g_Wdl);
    cudaGetSymbolAddress((void**)&yh,   g_yh);
    cudaGetSymbolAddress((void**)&Woh,  g_Woh);

    const int SMEM1 = 3 * (1 * A_PL + 1 * B_PL) * 2;
    const int SMEM3 = 2 * (2 * A_PL + 2 * B_PL) * 2;
    cudaFuncSetAttribute((const void*)mma_gemm<1, 3>,
                         cudaFuncAttributeMaxDynamicSharedMemorySize, SMEM1);
    cudaFuncSetAttribute((const void*)mma_gemm<3, 2>,
                         cudaFuncAttributeMaxDynamicSharedMemorySize, SMEM3);

    // 0) all input conversions (ILP x4)
    prep_kernel<<<(SEG5 + 1023) / 1024, 256>>>(
        (const float4*)x, (const float4*)W_in, (const float4*)W_dt,
        (const float4*)W_out, W_x,
        (uint2*)xh, (uint2*)Wih,
        (uint2*)Wdh, (uint2*)Wdl, (uint2*)Woh, (uint2*)Wxh, (uint2*)Wxl);

    // 1) xz = x @ W_in (1-term)
    mma_gemm<1, 3><<<dim3(NXZ / 128, MROWS / 128, 1), 256, SMEM1>>>(
        xh, nullptr, Wih, nullptr, xz, DM, DM, NXZ, NXZ, 0, nullptr);

    // 2) conv + SiLU (+ fp16 split), sliding-window x4 in l
    conv_silu_kernel<<<(MROWS * DI / 4 + 255) / 256, 256>>>(
        xz, conv_w, conv_b, xc, xch, xcl);

    // 3) dbl = xc @ W_x_padded (3-term), K-split 8
    mma_gemm<3, 2><<<dim3(1, MROWS / 128, 8), 256, SMEM3>>>(
        xch, xcl, Wxh, Wxl, dblp, DI / 8, DI, NDP, NDP,
        (size_t)MROWS * NDP, nullptr);

    // 4) reduce partials + compact fp16 of dt-rank slice
    reduce_dbl_kernel<<<(MROWS * NDP + 255) / 256, 256>>>(dblp, dbl, dbh, dbll);

    // 5) dt = softplus(dbl[:,:64] @ W_dt + b_dt) (3-term)
    mma_gemm<3, 2><<<dim3(DI / 128, MROWS / 128, 1), 256, SMEM3>>>(
        dbh, dbll, Wdh, Wdl, dtb, DTR, DTR, DI, DI, 0, b_dt);

    // 6) selective scan v3 -> y (fp16 hi), 4 lanes/channel, 64-thread blocks
    scan_kernel<<<(BC * DI * 4) / 64, 64>>>(dtb, xc, dbl, xz, A_log, D_par, yh);

    // 7) out = y @ W_out (1-term), K-split 2 -> slabs
    mma_gemm<1, 3><<<dim3(DM / 128, MROWS / 128, 2), 256, SMEM1>>>(
        yh, nullptr, Woh, nullptr, osp, DI / 2, DI, DM, DM,
        (size_t)MROWS * DM, nullptr);

    // 8) out = slab0 + slab1
    reduce_out_kernel<<<(MROWS * DM / 4 + 255) / 256, 256>>>(
        (const float4*)osp, (const float4*)(osp + (size_t)MROWS * DM),
        (float4*)out, MROWS * DM / 4);
}